// round 2
// baseline (speedup 1.0000x reference)
#include <cuda_runtime.h>

typedef unsigned long long ull;
typedef long long ll;

#define BATCH 4
#define SEQ   2048
#define DMODEL 1024
#define EE    256
#define HH    4
#define DKK   64
#define NSC   4

// ---------------- f32x2 packed-FMA primitives (sm_10x) ----------------
__device__ __forceinline__ ull pack2(float lo, float hi) {
    ull r; asm("mov.b64 %0,{%1,%2};" : "=l"(r) : "f"(lo), "f"(hi)); return r;
}
__device__ __forceinline__ void unpack2(float& lo, float& hi, ull v) {
    asm("mov.b64 {%0,%1},%2;" : "=f"(lo), "=f"(hi) : "l"(v));
}
__device__ __forceinline__ ull ffma2(ull a, ull b, ull c) {
    ull d; asm("fma.rn.f32x2 %0,%1,%2,%3;" : "=l"(d) : "l"(a), "l"(b), "l"(c)); return d;
}

// -------- static device scratch --------
__device__ float g_Xs [BATCH * SEQ * EE];
__device__ float g_QKV[BATCH * SEQ * 3 * EE];
__device__ float g_SC [(ll)BATCH * HH * SEQ * SEQ];
__device__ float g_O  [BATCH * SEQ * EE];
__device__ float g_Y  [(BATCH * (SEQ + SEQ/2 + SEQ/4 + SEQ/8)) * EE];
__device__ float g_Z  [BATCH * SEQ * DMODEL];
__device__ float g_ZF [BATCH * SEQ * DMODEL];

// ---------------- generic GEMM, 128x128 tile, f32x2 inner ----------------
// C = A*B + bias.  A rows via off(r) = (r/rowsPerChunk)*chunkStride + (r%rowsPerChunk)*rowStride
// M %128 == 0, N %128 == 0, K %16 == 0.
__global__ __launch_bounds__(256, 2)
void gemm_f32x2_kernel(int M, int N, int K,
    const float* __restrict__ A, ll aRowStride, int aRowsPerChunk, ll aChunkStride,
    const float* __restrict__ B, int ldB,
    const float* __restrict__ bias,
    float* __restrict__ C, int ldC)
{
    __shared__ float As[16][132];   // [k][row]
    __shared__ float Bs[16][132];   // [k][col]
    const int tid = threadIdx.x;
    const int tx = tid & 15, ty = tid >> 4;
    const int rowBase = blockIdx.y * 128;
    const int colBase = blockIdx.x * 128;

    ull acc[8][4] = {};

    for (int k0 = 0; k0 < K; k0 += 16) {
        #pragma unroll
        for (int i = 0; i < 2; i++) {
            int lin = tid + i * 256;
            int r = lin >> 2, c4 = lin & 3;
            int gr = rowBase + r;
            ll off = (ll)(gr / aRowsPerChunk) * aChunkStride
                   + (ll)(gr % aRowsPerChunk) * aRowStride + k0 + c4 * 4;
            float4 v = *(const float4*)(A + off);
            As[c4*4+0][r] = v.x; As[c4*4+1][r] = v.y;
            As[c4*4+2][r] = v.z; As[c4*4+3][r] = v.w;
        }
        #pragma unroll
        for (int i = 0; i < 2; i++) {
            int lin = tid + i * 256;
            int r = lin >> 5, c = (lin & 31) * 4;
            *(float4*)&Bs[r][c] = *(const float4*)(B + (ll)(k0 + r) * ldB + colBase + c);
        }
        __syncthreads();
        #pragma unroll
        for (int kk = 0; kk < 16; kk++) {
            float4 a0 = *(const float4*)&As[kk][ty * 8];
            float4 a1 = *(const float4*)&As[kk][ty * 8 + 4];
            ulonglong2 bv0 = *(const ulonglong2*)&Bs[kk][tx * 8];
            ulonglong2 bv1 = *(const ulonglong2*)&Bs[kk][tx * 8 + 4];
            float av[8] = {a0.x, a0.y, a0.z, a0.w, a1.x, a1.y, a1.z, a1.w};
            #pragma unroll
            for (int r = 0; r < 8; r++) {
                ull ad = pack2(av[r], av[r]);
                acc[r][0] = ffma2(ad, bv0.x, acc[r][0]);
                acc[r][1] = ffma2(ad, bv0.y, acc[r][1]);
                acc[r][2] = ffma2(ad, bv1.x, acc[r][2]);
                acc[r][3] = ffma2(ad, bv1.y, acc[r][3]);
            }
        }
        __syncthreads();
    }
    #pragma unroll
    for (int r = 0; r < 8; r++) {
        int gr = rowBase + ty * 8 + r;
        float o[8];
        #pragma unroll
        for (int p = 0; p < 4; p++) unpack2(o[2*p], o[2*p+1], acc[r][p]);
        #pragma unroll
        for (int j = 0; j < 8; j++) o[j] += bias[colBase + tx * 8 + j];
        float4 v0 = {o[0], o[1], o[2], o[3]};
        float4 v1 = {o[4], o[5], o[6], o[7]};
        *(float4*)(C + (ll)gr * ldC + colBase + tx * 8)     = v0;
        *(float4*)(C + (ll)gr * ldC + colBase + tx * 8 + 4) = v1;
    }
}

// ---------------- scores: S = (Q K^T) * 0.125, 128x128 tile ----------------
__global__ __launch_bounds__(256, 2)
void scores_f32x2_kernel(int L, const float* __restrict__ qkv, float* __restrict__ SC)
{
    const int bh = blockIdx.z;
    const int b = bh >> 2, h = bh & 3;
    const float* Q  = qkv + (ll)b * L * 768 + h * 64;
    const float* Km = Q + 256;
    float* Cb = SC + (ll)bh * L * L;

    __shared__ float Qs[16][132];
    __shared__ float Ks[16][132];
    const int tid = threadIdx.x;
    const int tx = tid & 15, ty = tid >> 4;
    const int rowBase = blockIdx.y * 128;
    const int colBase = blockIdx.x * 128;

    ull acc[8][4] = {};

    for (int k0 = 0; k0 < 64; k0 += 16) {
        #pragma unroll
        for (int i = 0; i < 2; i++) {
            int lin = tid + i * 256;
            int r = lin >> 2, c4 = lin & 3;
            float4 v = *(const float4*)(Q  + (ll)(rowBase + r) * 768 + k0 + c4 * 4);
            Qs[c4*4+0][r] = v.x; Qs[c4*4+1][r] = v.y;
            Qs[c4*4+2][r] = v.z; Qs[c4*4+3][r] = v.w;
            float4 w = *(const float4*)(Km + (ll)(colBase + r) * 768 + k0 + c4 * 4);
            Ks[c4*4+0][r] = w.x; Ks[c4*4+1][r] = w.y;
            Ks[c4*4+2][r] = w.z; Ks[c4*4+3][r] = w.w;
        }
        __syncthreads();
        #pragma unroll
        for (int kk = 0; kk < 16; kk++) {
            float4 a0 = *(const float4*)&Qs[kk][ty * 8];
            float4 a1 = *(const float4*)&Qs[kk][ty * 8 + 4];
            ulonglong2 bv0 = *(const ulonglong2*)&Ks[kk][tx * 8];
            ulonglong2 bv1 = *(const ulonglong2*)&Ks[kk][tx * 8 + 4];
            float av[8] = {a0.x, a0.y, a0.z, a0.w, a1.x, a1.y, a1.z, a1.w};
            #pragma unroll
            for (int r = 0; r < 8; r++) {
                ull ad = pack2(av[r], av[r]);
                acc[r][0] = ffma2(ad, bv0.x, acc[r][0]);
                acc[r][1] = ffma2(ad, bv0.y, acc[r][1]);
                acc[r][2] = ffma2(ad, bv1.x, acc[r][2]);
                acc[r][3] = ffma2(ad, bv1.y, acc[r][3]);
            }
        }
        __syncthreads();
    }
    #pragma unroll
    for (int r = 0; r < 8; r++) {
        int gq = rowBase + ty * 8 + r;
        float o[8];
        #pragma unroll
        for (int p = 0; p < 4; p++) unpack2(o[2*p], o[2*p+1], acc[r][p]);
        float4 v0 = {o[0]*0.125f, o[1]*0.125f, o[2]*0.125f, o[3]*0.125f};
        float4 v1 = {o[4]*0.125f, o[5]*0.125f, o[6]*0.125f, o[7]*0.125f};
        *(float4*)(Cb + (ll)gq * L + colBase + tx * 8)     = v0;
        *(float4*)(Cb + (ll)gq * L + colBase + tx * 8 + 4) = v1;
    }
}

// ---------------- PV: O[.,h*64..] = P @ V, 128x64 tile ----------------
__global__ __launch_bounds__(256, 2)
void pv_f32x2_kernel(int L, const float* __restrict__ P,
                     const float* __restrict__ qkv, float* __restrict__ O)
{
    const int bh = blockIdx.z;
    const int b = bh >> 2, h = bh & 3;
    const float* Pb = P + (ll)bh * L * L;
    const float* V  = qkv + (ll)b * L * 768 + 512 + h * 64;
    float* Cb = O + (ll)b * L * EE + h * 64;
    const int rowBase = blockIdx.y * 128;

    __shared__ float Ps[16][132];
    __shared__ float Vs[16][68];
    const int tid = threadIdx.x;
    const int tx = tid & 7, ty = tid >> 3;   // ty 0..31, 4 rows each; tx 0..7, 8 cols each

    ull acc[4][4] = {};

    for (int k0 = 0; k0 < L; k0 += 16) {
        #pragma unroll
        for (int i = 0; i < 2; i++) {
            int lin = tid + i * 256;
            int r = lin >> 2, c4 = lin & 3;
            float4 v = *(const float4*)(Pb + (ll)(rowBase + r) * L + k0 + c4 * 4);
            Ps[c4*4+0][r] = v.x; Ps[c4*4+1][r] = v.y;
            Ps[c4*4+2][r] = v.z; Ps[c4*4+3][r] = v.w;
        }
        {
            int r = tid >> 4, c = (tid & 15) * 4;
            *(float4*)&Vs[r][c] = *(const float4*)(V + (ll)(k0 + r) * 768 + c);
        }
        __syncthreads();
        #pragma unroll
        for (int kk = 0; kk < 16; kk++) {
            float4 a = *(const float4*)&Ps[kk][ty * 4];
            ulonglong2 bv0 = *(const ulonglong2*)&Vs[kk][tx * 8];
            ulonglong2 bv1 = *(const ulonglong2*)&Vs[kk][tx * 8 + 4];
            float av[4] = {a.x, a.y, a.z, a.w};
            #pragma unroll
            for (int r = 0; r < 4; r++) {
                ull ad = pack2(av[r], av[r]);
                acc[r][0] = ffma2(ad, bv0.x, acc[r][0]);
                acc[r][1] = ffma2(ad, bv0.y, acc[r][1]);
                acc[r][2] = ffma2(ad, bv1.x, acc[r][2]);
                acc[r][3] = ffma2(ad, bv1.y, acc[r][3]);
            }
        }
        __syncthreads();
    }
    #pragma unroll
    for (int r = 0; r < 4; r++) {
        int gr = rowBase + ty * 4 + r;
        float o[8];
        #pragma unroll
        for (int p = 0; p < 4; p++) unpack2(o[2*p], o[2*p+1], acc[r][p]);
        float4 v0 = {o[0], o[1], o[2], o[3]};
        float4 v1 = {o[4], o[5], o[6], o[7]};
        *(float4*)(Cb + (ll)gr * EE + tx * 8)     = v0;
        *(float4*)(Cb + (ll)gr * EE + tx * 8 + 4) = v1;
    }
}

// ---------------- fused softmax + w0 for scale 0 (L=2048) ----------------
__global__ void softmax_w0_kernel(float* __restrict__ SC, float* __restrict__ w0)
{
    const int b = blockIdx.x >> 11;
    const int q = blockIdx.x & 2047;
    const int tid = threadIdx.x;
    __shared__ float red[8];
    float wacc[8] = {0.f, 0.f, 0.f, 0.f, 0.f, 0.f, 0.f, 0.f};

    #pragma unroll
    for (int h = 0; h < 4; h++) {
        float* p = SC + ((ll)(b * 4 + h) * 2048 + q) * 2048;
        float4 u0 = ((const float4*)p)[tid];
        float4 u1 = ((const float4*)p)[tid + 256];
        float v[8] = {u0.x, u0.y, u0.z, u0.w, u1.x, u1.y, u1.z, u1.w};
        float m = v[0];
        #pragma unroll
        for (int i = 1; i < 8; i++) m = fmaxf(m, v[i]);
        #pragma unroll
        for (int o = 16; o; o >>= 1) m = fmaxf(m, __shfl_xor_sync(0xffffffffu, m, o));
        if ((tid & 31) == 0) red[tid >> 5] = m;
        __syncthreads();
        float mt = red[0];
        #pragma unroll
        for (int k = 1; k < 8; k++) mt = fmaxf(mt, red[k]);
        __syncthreads();
        float s = 0.f;
        #pragma unroll
        for (int i = 0; i < 8; i++) { v[i] = __expf(v[i] - mt); s += v[i]; }
        #pragma unroll
        for (int o = 16; o; o >>= 1) s += __shfl_xor_sync(0xffffffffu, s, o);
        if ((tid & 31) == 0) red[tid >> 5] = s;
        __syncthreads();
        float st = 0.f;
        #pragma unroll
        for (int k = 0; k < 8; k++) st += red[k];
        __syncthreads();
        const float inv = 1.f / st;
        #pragma unroll
        for (int i = 0; i < 8; i++) { v[i] *= inv; wacc[i] += v[i]; }
        float4 o0 = {v[0], v[1], v[2], v[3]};
        float4 o1 = {v[4], v[5], v[6], v[7]};
        ((float4*)p)[tid] = o0;
        ((float4*)p)[tid + 256] = o1;
    }
    float* wr = w0 + ((ll)b * 2048 + q) * 2048;
    float4 o0 = {wacc[0]*0.25f, wacc[1]*0.25f, wacc[2]*0.25f, wacc[3]*0.25f};
    float4 o1 = {wacc[4]*0.25f, wacc[5]*0.25f, wacc[6]*0.25f, wacc[7]*0.25f};
    ((float4*)wr)[tid] = o0;
    ((float4*)wr)[tid + 256] = o1;
}

// ---------------- plain softmax for scales 1..3 ----------------
__global__ void softmax_kernel(float* __restrict__ scores, int L)
{
    const ll row = blockIdx.x;
    float* p = scores + row * (ll)L;
    const int tid = threadIdx.x;
    const int per = L >> 8;
    float v[8];

    float m = -1e30f;
    #pragma unroll 8
    for (int i = 0; i < per; i++) { v[i] = p[tid + i * 256]; m = fmaxf(m, v[i]); }

    __shared__ float red[8];
    #pragma unroll
    for (int o = 16; o; o >>= 1) m = fmaxf(m, __shfl_xor_sync(0xffffffffu, m, o));
    if ((tid & 31) == 0) red[tid >> 5] = m;
    __syncthreads();
    float mt = red[0];
    #pragma unroll
    for (int k = 1; k < 8; k++) mt = fmaxf(mt, red[k]);
    __syncthreads();

    float s = 0.f;
    #pragma unroll 8
    for (int i = 0; i < per; i++) { v[i] = __expf(v[i] - mt); s += v[i]; }
    #pragma unroll
    for (int o = 16; o; o >>= 1) s += __shfl_xor_sync(0xffffffffu, s, o);
    if ((tid & 31) == 0) red[tid >> 5] = s;
    __syncthreads();
    float st = 0.f;
    #pragma unroll
    for (int k = 0; k < 8; k++) st += red[k];
    const float inv = 1.f / st;
    #pragma unroll 8
    for (int i = 0; i < per; i++) p[tid + i * 256] = v[i] * inv;
}

// ---------------- upsample + concat into Z ----------------
__global__ void upsample_kernel(const float* __restrict__ Y, float* __restrict__ Z)
{
    ll idx = (ll)blockIdx.x * 256 + threadIdx.x;
    int c = (int)(idx & (DMODEL - 1));
    ll bt = idx >> 10;
    int t = (int)(bt & (SEQ - 1));
    int b = (int)(bt >> 11);
    int i = c >> 8;
    int cc = c & 255;
    int L = SEQ >> i;
    int k = t >> i;
    int j = t & ((1 << i) - 1);
    float alpha = (float)j / (float)(1 << i);

    const int yrowoff[4] = {0, BATCH * SEQ, BATCH * SEQ + BATCH * SEQ / 2,
                            BATCH * SEQ + BATCH * SEQ / 2 + BATCH * SEQ / 4};
    ll base = ((ll)yrowoff[i] + (ll)b * L + k) * EE + cc;
    float v = Y[base];
    float vn = (k + 1 < L) ? Y[base + EE] : 0.f;
    Z[idx] = (1.f - alpha) * v + alpha * vn;
}

// ---------------- layernorm rows of 1024 ----------------
__global__ void layernorm_kernel(const float* __restrict__ Zf,
                                 const float* __restrict__ gam, const float* __restrict__ bet,
                                 float* __restrict__ out)
{
    const ll row = blockIdx.x;
    const float* p = Zf + row * DMODEL;
    const int tid = threadIdx.x;
    float v[4];
    float s = 0.f, s2 = 0.f;
    #pragma unroll
    for (int i = 0; i < 4; i++) {
        v[i] = p[tid + i * 256];
        s += v[i]; s2 += v[i] * v[i];
    }
    __shared__ float rs[8], rs2[8];
    #pragma unroll
    for (int o = 16; o; o >>= 1) { s += __shfl_xor_sync(0xffffffffu, s, o);
                                   s2 += __shfl_xor_sync(0xffffffffu, s2, o); }
    if ((tid & 31) == 0) { rs[tid >> 5] = s; rs2[tid >> 5] = s2; }
    __syncthreads();
    float ts = 0.f, ts2 = 0.f;
    #pragma unroll
    for (int k = 0; k < 8; k++) { ts += rs[k]; ts2 += rs2[k]; }
    const float mu = ts * (1.f / DMODEL);
    const float var = ts2 * (1.f / DMODEL) - mu * mu;
    const float inv = rsqrtf(var + 1e-5f);
    #pragma unroll
    for (int i = 0; i < 4; i++) {
        int c = tid + i * 256;
        out[row * DMODEL + c] = (v[i] - mu) * inv * gam[c] + bet[c];
    }
}

// ---------------- launch ----------------
extern "C" void kernel_launch(void* const* d_in, const int* in_sizes, int n_in,
                              void* d_out, int out_size)
{
    (void)in_sizes; (void)n_in; (void)out_size;
    const float* x     = (const float*)d_in[0];
    const float* projW = (const float*)d_in[1];
    const float* projb = (const float*)d_in[2];
    const float* inW   = (const float*)d_in[3];
    const float* inb   = (const float*)d_in[4];
    const float* outW  = (const float*)d_in[5];
    const float* outb  = (const float*)d_in[6];
    const float* fusW  = (const float*)d_in[7];
    const float* fusb  = (const float*)d_in[8];
    const float* lng   = (const float*)d_in[9];
    const float* lnb   = (const float*)d_in[10];

    float* fused = (float*)d_out;
    float* w0 = fused + (ll)BATCH * SEQ * DMODEL;

    float *Xs, *QKV, *SC, *O, *Y, *Z, *ZF;
    cudaGetSymbolAddress((void**)&Xs,  g_Xs);
    cudaGetSymbolAddress((void**)&QKV, g_QKV);
    cudaGetSymbolAddress((void**)&SC,  g_SC);
    cudaGetSymbolAddress((void**)&O,   g_O);
    cudaGetSymbolAddress((void**)&Y,   g_Y);
    cudaGetSymbolAddress((void**)&Z,   g_Z);
    cudaGetSymbolAddress((void**)&ZF,  g_ZF);

    const dim3 blk(256);
    int yoff = 0;
    for (int i = 0; i < NSC; i++) {
        const int s = 1 << i;
        const int L = SEQ >> i;
        const int rows = BATCH * L;

        // projection of subsampled rows: (rows,1024)@(1024,256)
        gemm_f32x2_kernel<<<dim3(EE / 128, rows / 128), blk>>>(
            rows, EE, DMODEL,
            x, (ll)s * DMODEL, L, (ll)SEQ * DMODEL,
            projW + (ll)i * DMODEL * EE, EE,
            projb + i * EE, Xs, EE);

        // qkv: (rows,256)@(256,768)
        gemm_f32x2_kernel<<<dim3(768 / 128, rows / 128), blk>>>(
            rows, 3 * EE, EE,
            Xs, (ll)EE, rows, 0LL,
            inW + (ll)i * EE * 3 * EE, 3 * EE,
            inb + i * 3 * EE, QKV, 3 * EE);

        // scores (scale folded in)
        scores_f32x2_kernel<<<dim3(L / 128, L / 128, BATCH * HH), blk>>>(L, QKV, SC);

        if (i == 0)
            softmax_w0_kernel<<<BATCH * SEQ, blk>>>(SC, w0);
        else
            softmax_kernel<<<BATCH * HH * L, blk>>>(SC, L);

        // PV
        pv_f32x2_kernel<<<dim3(1, L / 128, BATCH * HH), blk>>>(L, SC, QKV, O);

        // out proj: (rows,256)@(256,256)
        gemm_f32x2_kernel<<<dim3(EE / 128, rows / 128), blk>>>(
            rows, EE, EE,
            O, (ll)EE, rows, 0LL,
            outW + (ll)i * EE * EE, EE,
            outb + i * EE, Y + (ll)yoff * EE, EE);

        yoff += rows;
    }

    // upsample + concat
    upsample_kernel<<<(unsigned)(((ll)BATCH * SEQ * DMODEL) / 256), blk>>>(Y, Z);

    // fusion GEMM: (8192,1024)@(1024,1024)
    gemm_f32x2_kernel<<<dim3(DMODEL / 128, (BATCH * SEQ) / 128), blk>>>(
        BATCH * SEQ, DMODEL, DMODEL,
        Z, (ll)DMODEL, BATCH * SEQ, 0LL,
        fusW, DMODEL, fusb, ZF, DMODEL);

    // layernorm -> fused output
    layernorm_kernel<<<BATCH * SEQ, blk>>>(ZF, lng, lnb, fused);
}

// round 4
// speedup vs baseline: 1.4695x; 1.4695x over previous
#include <cuda_runtime.h>
#include <cuda_bf16.h>
#include <cstdint>

typedef long long ll;
typedef unsigned int u32;
typedef unsigned long long u64;

#define BATCH 4
#define SEQ   2048
#define DMODEL 1024
#define EE    256
#define NSC   4

// ================= static device scratch =================
__device__ __nv_bfloat16 g_xh [BATCH*SEQ*DMODEL], g_xl [BATCH*SEQ*DMODEL];
__device__ __nv_bfloat16 g_PWth[NSC*EE*DMODEL],   g_PWtl[NSC*EE*DMODEL];
__device__ __nv_bfloat16 g_IWth[NSC*768*EE],      g_IWtl[NSC*768*EE];
__device__ __nv_bfloat16 g_OWth[NSC*EE*EE],       g_OWtl[NSC*EE*EE];
__device__ __nv_bfloat16 g_FWth[DMODEL*DMODEL],   g_FWtl[DMODEL*DMODEL];
__device__ __nv_bfloat16 g_Xsh[BATCH*SEQ*EE],     g_Xsl[BATCH*SEQ*EE];
__device__ __nv_bfloat16 g_Qh [BATCH*SEQ*768],    g_Ql [BATCH*SEQ*768];
__device__ __nv_bfloat16 g_Vth[16*64*SEQ],        g_Vtl[16*64*SEQ];
__device__ float         g_SC [16ull*SEQ*SEQ];
__device__ __nv_bfloat16 g_Ph [16ull*SEQ*SEQ],    g_Pl [16ull*SEQ*SEQ];
__device__ __nv_bfloat16 g_Oh [BATCH*SEQ*EE],     g_Ol [BATCH*SEQ*EE];
__device__ float         g_Y  [(BATCH*(SEQ+SEQ/2+SEQ/4+SEQ/8))*EE];
__device__ __nv_bfloat16 g_Zh [BATCH*SEQ*DMODEL], g_Zl [BATCH*SEQ*DMODEL];
__device__ float         g_ZF [BATCH*SEQ*DMODEL];

// ================= PTX helpers (arch-neutral: ldmatrix + mma.sync) =================
__device__ __forceinline__ u32 su32(const void* p) {
    u32 a; asm("{ .reg .u64 t; cvta.to.shared.u64 t,%1; cvt.u32.u64 %0,t; }" : "=r"(a) : "l"(p));
    return a;
}
__device__ __forceinline__ void ldsm4(u32& r0, u32& r1, u32& r2, u32& r3, u32 addr) {
    asm volatile("ldmatrix.sync.aligned.m8n8.x4.shared.b16 {%0,%1,%2,%3},[%4];"
                 : "=r"(r0), "=r"(r1), "=r"(r2), "=r"(r3) : "r"(addr));
}
__device__ __forceinline__ void mma16816(float* c, const u32* a, const u32* b) {
    asm volatile("mma.sync.aligned.m16n8k16.row.col.f32.bf16.bf16.f32 "
                 "{%0,%1,%2,%3},{%4,%5,%6,%7},{%8,%9},{%0,%1,%2,%3};"
                 : "+f"(c[0]), "+f"(c[1]), "+f"(c[2]), "+f"(c[3])
                 : "r"(a[0]), "r"(a[1]), "r"(a[2]), "r"(a[3]), "r"(b[0]), "r"(b[1]));
}

// ================= unified tensor-core GEMM (mma.sync bf16) =================
// C[M x N] = sum over 3 segments of A_s(M x K) * B_s(N x K)^T, +bias, *outScale
// A row gr: (gr/rpc)*csA + (gr%rpc)*rsA ; z offsets: (z>>2)*q + (z&3)*r
// NB = 128: warps 2(m) x 4(n), warp tile 64x32. NB = 64: warps 4x2, tile 32x32.
template<int NB>
__global__ __launch_bounds__(256)
void tc_gemm(int Kseg, int rpc, ll rsA, ll csA,
             const __nv_bfloat16* __restrict__ a0, const __nv_bfloat16* __restrict__ a1,
             const __nv_bfloat16* __restrict__ a2, ll aZq, ll aZr,
             const __nv_bfloat16* __restrict__ b0, const __nv_bfloat16* __restrict__ b1,
             const __nv_bfloat16* __restrict__ b2, int ldB, ll bZq, ll bZr,
             const float* __restrict__ bias,
             float* __restrict__ Cf, __nv_bfloat16* __restrict__ Chi, __nv_bfloat16* __restrict__ Clo,
             int ldC, ll cZq, ll cZr, float outScale)
{
    constexpr int MW = (NB == 128) ? 4 : 2;       // m16-frags per warp
    constexpr int WM = (NB == 128) ? 2 : 4;       // warp grid m
    // warp grid n = 8/WM; n-frags per warp = 4 (32 cols)
    __shared__ __align__(16) __nv_bfloat16 sA[128 * 40];
    __shared__ __align__(16) __nv_bfloat16 sB[NB * 40];

    const int tid = threadIdx.x, wid = tid >> 5, lane = tid & 31;
    const int wm = wid % WM, wn = wid / WM;
    const int z = blockIdx.z;
    const int rowBase = blockIdx.y * 128, colBase = blockIdx.x * NB;
    const ll zA = (ll)(z >> 2) * aZq + (ll)(z & 3) * aZr;
    const ll zB = (ll)(z >> 2) * bZq + (ll)(z & 3) * bZr;
    const ll zC = (ll)(z >> 2) * cZq + (ll)(z & 3) * cZr;

    const __nv_bfloat16* As[3] = {a0, a1, a2};
    const __nv_bfloat16* Bs[3] = {b0, b1, b2};
    const int tps = Kseg >> 5;     // 32-elem K tiles per segment
    const u32 sAb = su32(sA), sBb = su32(sB);

    float acc[MW][4][4];
    #pragma unroll
    for (int i = 0; i < MW; i++)
        #pragma unroll
        for (int j = 0; j < 4; j++)
            #pragma unroll
            for (int c = 0; c < 4; c++) acc[i][j][c] = 0.f;

    // per-thread ldmatrix source offsets (element units within padded row of 40)
    const int aRowSel = ((lane >> 3) & 1) * 8 + (lane & 7);  // + mi*16
    const int aKSel   = (lane >> 4) * 8;                      // + ks*16
    const int bRowSel = (lane >> 4) * 8 + (lane & 7);         // + np*16
    const int bKSel   = ((lane >> 3) & 1) * 8;                // + ks*16

    for (int seg = 0; seg < 3; seg++) {
        const __nv_bfloat16* A = As[seg] + zA;
        const __nv_bfloat16* B = Bs[seg] + zB;
        for (int kt = 0; kt < tps; kt++) {
            // load A tile: 128 rows x 32 bf16 -> smem rows padded to 40
            #pragma unroll
            for (int p = 0; p < 2; p++) {
                int idx = tid + p * 256;
                int r = idx >> 2, ch = idx & 3;
                int gr = rowBase + r;
                ll off = (ll)(gr / rpc) * csA + (ll)(gr % rpc) * rsA + kt * 32 + ch * 8;
                *(uint4*)&sA[r * 40 + ch * 8] = *(const uint4*)(A + off);
            }
            // load B tile: NB rows x 32 bf16
            #pragma unroll
            for (int p = 0; p < NB / 64; p++) {
                int idx = tid + p * 256;
                int r = idx >> 2, ch = idx & 3;
                ll off = (ll)(colBase + r) * ldB + kt * 32 + ch * 8;
                *(uint4*)&sB[r * 40 + ch * 8] = *(const uint4*)(B + off);
            }
            __syncthreads();

            #pragma unroll
            for (int ks = 0; ks < 2; ks++) {
                u32 aF[MW][4], bF[4][2];
                #pragma unroll
                for (int mi = 0; mi < MW; mi++) {
                    int row = wm * (MW * 16) + mi * 16 + aRowSel;
                    int kc = ks * 16 + aKSel;
                    ldsm4(aF[mi][0], aF[mi][1], aF[mi][2], aF[mi][3],
                          sAb + (row * 40 + kc) * 2);
                }
                #pragma unroll
                for (int np = 0; np < 2; np++) {
                    int rowN = wn * 32 + np * 16 + bRowSel;
                    int kc = ks * 16 + bKSel;
                    ldsm4(bF[2*np][0], bF[2*np][1], bF[2*np+1][0], bF[2*np+1][1],
                          sBb + (rowN * 40 + kc) * 2);
                }
                #pragma unroll
                for (int mi = 0; mi < MW; mi++)
                    #pragma unroll
                    for (int ni = 0; ni < 4; ni++)
                        mma16816(acc[mi][ni], aF[mi], bF[ni]);
            }
            __syncthreads();
        }
    }

    // ---------------- epilogue ----------------
    const int gID = lane >> 2, tig = lane & 3;
    #pragma unroll
    for (int mi = 0; mi < MW; mi++) {
        #pragma unroll
        for (int ni = 0; ni < 4; ni++) {
            int gr0 = rowBase + wm * (MW * 16) + mi * 16 + gID;
            int gc  = colBase + wn * 32 + ni * 8 + tig * 2;
            float b0v = 0.f, b1v = 0.f;
            if (bias) { b0v = bias[gc]; b1v = bias[gc + 1]; }
            #pragma unroll
            for (int hrow = 0; hrow < 2; hrow++) {
                int gr = gr0 + hrow * 8;
                float v0 = acc[mi][ni][hrow*2+0] * outScale + b0v;
                float v1 = acc[mi][ni][hrow*2+1] * outScale + b1v;
                if (Cf) {
                    float2 o = {v0, v1};
                    *(float2*)(Cf + zC + (ll)gr * ldC + gc) = o;
                }
                if (Chi) {
                    __nv_bfloat16 h0 = __float2bfloat16(v0), h1 = __float2bfloat16(v1);
                    __nv_bfloat162 hp; hp.x = h0; hp.y = h1;
                    __nv_bfloat162 lp;
                    lp.x = __float2bfloat16(v0 - __bfloat162float(h0));
                    lp.y = __float2bfloat16(v1 - __bfloat162float(h1));
                    *(u32*)(Chi + zC + (ll)gr * ldC + gc) = *(u32*)&hp;
                    *(u32*)(Clo + zC + (ll)gr * ldC + gc) = *(u32*)&lp;
                }
            }
        }
    }
}

// ================= converts =================
__global__ void split_kernel(const float* __restrict__ in,
                             __nv_bfloat16* __restrict__ oh, __nv_bfloat16* __restrict__ ol, ll n)
{
    ll i = (ll)blockIdx.x * 256 + threadIdx.x;
    if (i >= n) return;
    float v = in[i];
    __nv_bfloat16 h = __float2bfloat16(v);
    oh[i] = h;
    ol[i] = __float2bfloat16(v - __bfloat162float(h));
}

__global__ void transpose_split(const float* __restrict__ W, ll zIn,
                                __nv_bfloat16* __restrict__ oh, __nv_bfloat16* __restrict__ ol, ll zOut,
                                int K, int N)
{
    __shared__ float tile[32][33];
    const int z = blockIdx.z;
    const float* in = W + (ll)z * zIn;
    const int n0 = blockIdx.x * 32, k0 = blockIdx.y * 32;
    const int tx = threadIdx.x, ty = threadIdx.y;
    #pragma unroll
    for (int i = 0; i < 32; i += 8)
        tile[ty + i][tx] = in[(ll)(k0 + ty + i) * N + n0 + tx];
    __syncthreads();
    #pragma unroll
    for (int i = 0; i < 32; i += 8) {
        float v = tile[tx][ty + i];
        ll o = (ll)z * zOut + (ll)(n0 + ty + i) * K + k0 + tx;
        __nv_bfloat16 h = __float2bfloat16(v);
        oh[o] = h;
        ol[o] = __float2bfloat16(v - __bfloat162float(h));
    }
}

__global__ void vtrans_kernel(const __nv_bfloat16* __restrict__ qh, const __nv_bfloat16* __restrict__ ql,
                              __nv_bfloat16* __restrict__ vh, __nv_bfloat16* __restrict__ vl, int L)
{
    __shared__ __nv_bfloat16 t0[32][33], t1[32][33];
    const int bh = blockIdx.z, b = bh >> 2, h = bh & 3;
    const int k0 = blockIdx.x * 32, c0 = blockIdx.y * 32;
    const int tx = threadIdx.x, ty = threadIdx.y;
    const __nv_bfloat16* s0 = qh + (ll)b * L * 768 + 512 + h * 64;
    const __nv_bfloat16* s1 = ql + (ll)b * L * 768 + 512 + h * 64;
    #pragma unroll
    for (int i = 0; i < 32; i += 8) {
        t0[ty + i][tx] = s0[(ll)(k0 + ty + i) * 768 + c0 + tx];
        t1[ty + i][tx] = s1[(ll)(k0 + ty + i) * 768 + c0 + tx];
    }
    __syncthreads();
    const ll ob = (ll)bh * 64 * L;
    #pragma unroll
    for (int i = 0; i < 32; i += 8) {
        ll o = ob + (ll)(c0 + ty + i) * L + k0 + tx;
        vh[o] = t0[tx][ty + i];
        vl[o] = t1[tx][ty + i];
    }
}

// ================= softmax =================
__global__ void softmax_w0_kernel(const float* __restrict__ SC,
                                  __nv_bfloat16* __restrict__ Ph, __nv_bfloat16* __restrict__ Pl,
                                  float* __restrict__ w0)
{
    const int b = blockIdx.x >> 11, q = blockIdx.x & 2047, tid = threadIdx.x;
    __shared__ float red[8];
    float wacc[8] = {0.f,0.f,0.f,0.f,0.f,0.f,0.f,0.f};

    #pragma unroll
    for (int h = 0; h < 4; h++) {
        const ll ro = ((ll)(b * 4 + h) * 2048 + q) * 2048;
        const float* p = SC + ro;
        float4 u0 = ((const float4*)p)[tid];
        float4 u1 = ((const float4*)p)[tid + 256];
        float v[8] = {u0.x,u0.y,u0.z,u0.w,u1.x,u1.y,u1.z,u1.w};
        float m = v[0];
        #pragma unroll
        for (int i = 1; i < 8; i++) m = fmaxf(m, v[i]);
        #pragma unroll
        for (int o = 16; o; o >>= 1) m = fmaxf(m, __shfl_xor_sync(0xffffffffu, m, o));
        if ((tid & 31) == 0) red[tid >> 5] = m;
        __syncthreads();
        float mt = red[0];
        #pragma unroll
        for (int k = 1; k < 8; k++) mt = fmaxf(mt, red[k]);
        __syncthreads();
        float s = 0.f;
        #pragma unroll
        for (int i = 0; i < 8; i++) { v[i] = __expf(v[i] - mt); s += v[i]; }
        #pragma unroll
        for (int o = 16; o; o >>= 1) s += __shfl_xor_sync(0xffffffffu, s, o);
        if ((tid & 31) == 0) red[tid >> 5] = s;
        __syncthreads();
        float st = 0.f;
        #pragma unroll
        for (int k = 0; k < 8; k++) st += red[k];
        __syncthreads();
        const float inv = 1.f / st;
        #pragma unroll
        for (int i = 0; i < 8; i++) { v[i] *= inv; wacc[i] += v[i]; }
        u32 hp[4], lp[4];
        #pragma unroll
        for (int j = 0; j < 4; j++) {
            float a = v[j*2], c = v[j*2+1];
            __nv_bfloat16 ha = __float2bfloat16(a), hc = __float2bfloat16(c);
            __nv_bfloat162 hh; hh.x = ha; hh.y = hc;
            __nv_bfloat162 lo; lo.x = __float2bfloat16(a - __bfloat162float(ha));
            lo.y = __float2bfloat16(c - __bfloat162float(hc));
            hp[j] = *(u32*)&hh; lp[j] = *(u32*)&lo;
        }
        uint2 h0 = {hp[0], hp[1]}, h1 = {hp[2], hp[3]};
        uint2 l0 = {lp[0], lp[1]}, l1 = {lp[2], lp[3]};
        ((uint2*)(Ph + ro))[tid] = h0;        ((uint2*)(Pl + ro))[tid] = l0;
        ((uint2*)(Ph + ro))[tid + 256] = h1;  ((uint2*)(Pl + ro))[tid + 256] = l1;
    }
    float* wr = w0 + ((ll)b * 2048 + q) * 2048;
    float4 o0 = {wacc[0]*0.25f, wacc[1]*0.25f, wacc[2]*0.25f, wacc[3]*0.25f};
    float4 o1 = {wacc[4]*0.25f, wacc[5]*0.25f, wacc[6]*0.25f, wacc[7]*0.25f};
    ((float4*)wr)[tid] = o0;
    ((float4*)wr)[tid + 256] = o1;
}

__global__ void softmax_bf16_kernel(const float* __restrict__ SC,
                                    __nv_bfloat16* __restrict__ Ph, __nv_bfloat16* __restrict__ Pl, int L)
{
    const ll row = blockIdx.x;
    const float* p = SC + row * (ll)L;
    const int tid = threadIdx.x;
    const int per = L >> 8;
    float v[4];
    float m = -1e30f;
    for (int i = 0; i < per; i++) { v[i] = p[tid + i * 256]; m = fmaxf(m, v[i]); }
    __shared__ float red[8];
    #pragma unroll
    for (int o = 16; o; o >>= 1) m = fmaxf(m, __shfl_xor_sync(0xffffffffu, m, o));
    if ((tid & 31) == 0) red[tid >> 5] = m;
    __syncthreads();
    float mt = red[0];
    #pragma unroll
    for (int k = 1; k < 8; k++) mt = fmaxf(mt, red[k]);
    __syncthreads();
    float s = 0.f;
    for (int i = 0; i < per; i++) { v[i] = __expf(v[i] - mt); s += v[i]; }
    #pragma unroll
    for (int o = 16; o; o >>= 1) s += __shfl_xor_sync(0xffffffffu, s, o);
    if ((tid & 31) == 0) red[tid >> 5] = s;
    __syncthreads();
    float st = 0.f;
    #pragma unroll
    for (int k = 0; k < 8; k++) st += red[k];
    const float inv = 1.f / st;
    for (int i = 0; i < per; i++) {
        float val = v[i] * inv;
        __nv_bfloat16 h = __float2bfloat16(val);
        Ph[row * (ll)L + tid + i * 256] = h;
        Pl[row * (ll)L + tid + i * 256] = __float2bfloat16(val - __bfloat162float(h));
    }
}

// ================= upsample + concat -> Z hi/lo =================
__global__ void upsample_kernel(const float* __restrict__ Y,
                                __nv_bfloat16* __restrict__ Zh, __nv_bfloat16* __restrict__ Zl)
{
    ll idx = (ll)blockIdx.x * 256 + threadIdx.x;
    int c = (int)(idx & (DMODEL - 1));
    ll bt = idx >> 10;
    int t = (int)(bt & (SEQ - 1));
    int b = (int)(bt >> 11);
    int i = c >> 8;
    int cc = c & 255;
    int L = SEQ >> i;
    int k = t >> i;
    int j = t & ((1 << i) - 1);
    float alpha = (float)j / (float)(1 << i);
    const int yrowoff[4] = {0, BATCH*SEQ, BATCH*SEQ + BATCH*SEQ/2,
                            BATCH*SEQ + BATCH*SEQ/2 + BATCH*SEQ/4};
    ll base = ((ll)yrowoff[i] + (ll)b * L + k) * EE + cc;
    float v = Y[base];
    float vn = (k + 1 < L) ? Y[base + EE] : 0.f;
    float z = (1.f - alpha) * v + alpha * vn;
    __nv_bfloat16 h = __float2bfloat16(z);
    Zh[idx] = h;
    Zl[idx] = __float2bfloat16(z - __bfloat162float(h));
}

// ================= layernorm =================
__global__ void layernorm_kernel(const float* __restrict__ Zf,
                                 const float* __restrict__ gam, const float* __restrict__ bet,
                                 float* __restrict__ out)
{
    const ll row = blockIdx.x;
    const float* p = Zf + row * DMODEL;
    const int tid = threadIdx.x;
    float v[4];
    float s = 0.f, s2 = 0.f;
    #pragma unroll
    for (int i = 0; i < 4; i++) { v[i] = p[tid + i * 256]; s += v[i]; s2 += v[i] * v[i]; }
    __shared__ float rs[8], rs2[8];
    #pragma unroll
    for (int o = 16; o; o >>= 1) { s += __shfl_xor_sync(0xffffffffu, s, o);
                                   s2 += __shfl_xor_sync(0xffffffffu, s2, o); }
    if ((tid & 31) == 0) { rs[tid >> 5] = s; rs2[tid >> 5] = s2; }
    __syncthreads();
    float ts = 0.f, ts2 = 0.f;
    #pragma unroll
    for (int k = 0; k < 8; k++) { ts += rs[k]; ts2 += rs2[k]; }
    const float mu = ts * (1.f / DMODEL);
    const float var = ts2 * (1.f / DMODEL) - mu * mu;
    const float inv = rsqrtf(var + 1e-5f);
    #pragma unroll
    for (int i = 0; i < 4; i++) {
        int c = tid + i * 256;
        out[row * DMODEL + c] = (v[i] - mu) * inv * gam[c] + bet[c];
    }
}

// ================= launch =================
extern "C" void kernel_launch(void* const* d_in, const int* in_sizes, int n_in,
                              void* d_out, int out_size)
{
    (void)in_sizes; (void)n_in; (void)out_size;
    const float* x     = (const float*)d_in[0];
    const float* projW = (const float*)d_in[1];
    const float* projb = (const float*)d_in[2];
    const float* inW   = (const float*)d_in[3];
    const float* inb   = (const float*)d_in[4];
    const float* outW  = (const float*)d_in[5];
    const float* outb  = (const float*)d_in[6];
    const float* fusW  = (const float*)d_in[7];
    const float* fusb  = (const float*)d_in[8];
    const float* lng   = (const float*)d_in[9];
    const float* lnb   = (const float*)d_in[10];

    float* fused = (float*)d_out;
    float* w0 = fused + (ll)BATCH * SEQ * DMODEL;

    __nv_bfloat16 *xh,*xl,*PWth,*PWtl,*IWth,*IWtl,*OWth,*OWtl,*FWth,*FWtl;
    __nv_bfloat16 *Xsh,*Xsl,*Qh,*Ql,*Vth,*Vtl,*Ph,*Pl,*Oh,*Ol,*Zh,*Zl;
    float *SC,*Y,*ZF;
    cudaGetSymbolAddress((void**)&xh, g_xh);   cudaGetSymbolAddress((void**)&xl, g_xl);
    cudaGetSymbolAddress((void**)&PWth, g_PWth); cudaGetSymbolAddress((void**)&PWtl, g_PWtl);
    cudaGetSymbolAddress((void**)&IWth, g_IWth); cudaGetSymbolAddress((void**)&IWtl, g_IWtl);
    cudaGetSymbolAddress((void**)&OWth, g_OWth); cudaGetSymbolAddress((void**)&OWtl, g_OWtl);
    cudaGetSymbolAddress((void**)&FWth, g_FWth); cudaGetSymbolAddress((void**)&FWtl, g_FWtl);
    cudaGetSymbolAddress((void**)&Xsh, g_Xsh); cudaGetSymbolAddress((void**)&Xsl, g_Xsl);
    cudaGetSymbolAddress((void**)&Qh, g_Qh);   cudaGetSymbolAddress((void**)&Ql, g_Ql);
    cudaGetSymbolAddress((void**)&Vth, g_Vth); cudaGetSymbolAddress((void**)&Vtl, g_Vtl);
    cudaGetSymbolAddress((void**)&Ph, g_Ph);   cudaGetSymbolAddress((void**)&Pl, g_Pl);
    cudaGetSymbolAddress((void**)&Oh, g_Oh);   cudaGetSymbolAddress((void**)&Ol, g_Ol);
    cudaGetSymbolAddress((void**)&Zh, g_Zh);   cudaGetSymbolAddress((void**)&Zl, g_Zl);
    cudaGetSymbolAddress((void**)&SC, g_SC);
    cudaGetSymbolAddress((void**)&Y, g_Y);
    cudaGetSymbolAddress((void**)&ZF, g_ZF);

    const dim3 blk(256);
    const dim3 tblk(32, 8);

    split_kernel<<<(unsigned)(((ll)BATCH*SEQ*DMODEL + 255) / 256), blk>>>(x, xh, xl, (ll)BATCH*SEQ*DMODEL);
    transpose_split<<<dim3(EE/32, DMODEL/32, NSC), tblk>>>(projW, (ll)DMODEL*EE, PWth, PWtl, (ll)EE*DMODEL, DMODEL, EE);
    transpose_split<<<dim3(768/32, EE/32, NSC), tblk>>>(inW, (ll)EE*768, IWth, IWtl, (ll)768*EE, EE, 768);
    transpose_split<<<dim3(EE/32, EE/32, NSC), tblk>>>(outW, (ll)EE*EE, OWth, OWtl, (ll)EE*EE, EE, EE);
    transpose_split<<<dim3(DMODEL/32, DMODEL/32, 1), tblk>>>(fusW, 0, FWth, FWtl, 0, DMODEL, DMODEL);

    int yoff = 0;
    for (int i = 0; i < NSC; i++) {
        const int s = 1 << i;
        const int L = SEQ >> i;
        const int rows = BATCH * L;
        const ll LL = (ll)L * L;

        // proj: (rows,1024)@(1024,256) -> Xs hi/lo
        tc_gemm<128><<<dim3(EE/128, rows/128, 1), blk>>>(
            DMODEL, L, (ll)s * DMODEL, (ll)SEQ * DMODEL,
            xh, xh, xl, 0, 0,
            PWth + (ll)i*EE*DMODEL, PWtl + (ll)i*EE*DMODEL, PWth + (ll)i*EE*DMODEL, DMODEL, 0, 0,
            projb + i * EE, nullptr, Xsh, Xsl, EE, 0, 0, 1.f);

        // qkv: (rows,256)@(256,768) -> Q hi/lo
        tc_gemm<128><<<dim3(768/128, rows/128, 1), blk>>>(
            EE, rows, (ll)EE, 0,
            Xsh, Xsh, Xsl, 0, 0,
            IWth + (ll)i*768*EE, IWtl + (ll)i*768*EE, IWth + (ll)i*768*EE, EE, 0, 0,
            inb + i * 768, nullptr, Qh, Ql, 768, 0, 0, 1.f);

        // V transpose
        vtrans_kernel<<<dim3(L/32, 2, 16), tblk>>>(Qh, Ql, Vth, Vtl, L);

        // scores: per bh, (L,64)@(L,64)^T -> SC fp32, scale 0.125
        tc_gemm<128><<<dim3(L/128, L/128, 16), blk>>>(
            64, L, 768, 0,
            Qh, Qh, Ql, (ll)L * 768, 64,
            Qh + 256, Ql + 256, Qh + 256, 768, (ll)L * 768, 64,
            nullptr, SC, nullptr, nullptr, L, 4 * LL, LL, 0.125f);

        // softmax
        if (i == 0)
            softmax_w0_kernel<<<BATCH * SEQ, blk>>>(SC, Ph, Pl, w0);
        else
            softmax_bf16_kernel<<<BATCH * 4 * L, blk>>>(SC, Ph, Pl, L);

        // PV: per bh, (L,L)@(64,L)^T -> O hi/lo (col block h*64)
        tc_gemm<64><<<dim3(1, L/128, 16), blk>>>(
            L, L, (ll)L, 0,
            Ph, Ph, Pl, 4 * LL, LL,
            Vth, Vtl, Vth, L, (ll)256 * L, (ll)64 * L,
            nullptr, nullptr, Oh, Ol, EE, (ll)L * EE, 64, 1.f);

        // out proj: (rows,256)@(256,256) -> Y fp32
        tc_gemm<128><<<dim3(EE/128, rows/128, 1), blk>>>(
            EE, rows, (ll)EE, 0,
            Oh, Oh, Ol, 0, 0,
            OWth + (ll)i*EE*EE, OWtl + (ll)i*EE*EE, OWth + (ll)i*EE*EE, EE, 0, 0,
            outb + i * EE, Y + (ll)yoff * EE, nullptr, nullptr, EE, 0, 0, 1.f);

        yoff += rows;
    }

    // upsample + concat -> Z hi/lo
    upsample_kernel<<<(unsigned)(((ll)BATCH*SEQ*DMODEL) / 256), blk>>>(Y, Zh, Zl);

    // fusion: (8192,1024)@(1024,1024) -> ZF fp32
    tc_gemm<128><<<dim3(DMODEL/128, (BATCH*SEQ)/128, 1), blk>>>(
        DMODEL, BATCH * SEQ, (ll)DMODEL, 0,
        Zh, Zh, Zl, 0, 0,
        FWth, FWtl, FWth, DMODEL, 0, 0,
        fusb, ZF, nullptr, nullptr, DMODEL, 0, 0, 1.f);

    // layernorm -> fused output
    layernorm_kernel<<<BATCH * SEQ, blk>>>(ZF, lng, lnb, fused);
}

// round 5
// speedup vs baseline: 2.2366x; 1.5221x over previous
#include <cuda_runtime.h>
#include <cuda_bf16.h>
#include <cstdint>

typedef long long ll;
typedef unsigned int u32;
typedef unsigned long long u64;

#define BATCH 4
#define SEQ   2048
#define DMODEL 1024
#define EE    256
#define NSC   4

// ================= static device scratch =================
__device__ __nv_bfloat16 g_xh [BATCH*SEQ*DMODEL], g_xl [BATCH*SEQ*DMODEL];
__device__ __nv_bfloat16 g_PWth[NSC*EE*DMODEL],   g_PWtl[NSC*EE*DMODEL];
__device__ __nv_bfloat16 g_IWth[NSC*768*EE],      g_IWtl[NSC*768*EE];
__device__ __nv_bfloat16 g_OWth[NSC*EE*EE],       g_OWtl[NSC*EE*EE];
__device__ __nv_bfloat16 g_FWth[DMODEL*DMODEL],   g_FWtl[DMODEL*DMODEL];
__device__ __nv_bfloat16 g_Xsh[BATCH*SEQ*EE],     g_Xsl[BATCH*SEQ*EE];
__device__ __nv_bfloat16 g_Qh [BATCH*SEQ*768],    g_Ql [BATCH*SEQ*768];
__device__ __nv_bfloat16 g_Vth[16*64*SEQ],        g_Vtl[16*64*SEQ];
__device__ float         g_SC [16ull*SEQ*SEQ];
__device__ __nv_bfloat16 g_Ph [16ull*SEQ*SEQ],    g_Pl [16ull*SEQ*SEQ];
__device__ __nv_bfloat16 g_Oh [BATCH*SEQ*EE],     g_Ol [BATCH*SEQ*EE];
__device__ float         g_Y  [(BATCH*(SEQ+SEQ/2+SEQ/4+SEQ/8))*EE];
__device__ __nv_bfloat16 g_Zh [BATCH*SEQ*DMODEL], g_Zl [BATCH*SEQ*DMODEL];
__device__ float         g_ZF [BATCH*SEQ*DMODEL];

// ================= PTX helpers =================
__device__ __forceinline__ u32 su32(const void* p) {
    u32 a; asm("{ .reg .u64 t; cvta.to.shared.u64 t,%1; cvt.u32.u64 %0,t; }" : "=r"(a) : "l"(p));
    return a;
}
__device__ __forceinline__ void ldsm4(u32& r0, u32& r1, u32& r2, u32& r3, u32 addr) {
    asm volatile("ldmatrix.sync.aligned.m8n8.x4.shared.b16 {%0,%1,%2,%3},[%4];"
                 : "=r"(r0), "=r"(r1), "=r"(r2), "=r"(r3) : "r"(addr));
}
__device__ __forceinline__ void mma16816(float* c, const u32* a, const u32* b) {
    asm volatile("mma.sync.aligned.m16n8k16.row.col.f32.bf16.bf16.f32 "
                 "{%0,%1,%2,%3},{%4,%5,%6,%7},{%8,%9},{%0,%1,%2,%3};"
                 : "+f"(c[0]), "+f"(c[1]), "+f"(c[2]), "+f"(c[3])
                 : "r"(a[0]), "r"(a[1]), "r"(a[2]), "r"(a[3]), "r"(b[0]), "r"(b[1]));
}
__device__ __forceinline__ void cpa16(u32 saddr, const void* g) {
    asm volatile("cp.async.cg.shared.global [%0],[%1],16;" :: "r"(saddr), "l"(g));
}
#define CPA_COMMIT asm volatile("cp.async.commit_group;" ::: "memory")
#define CPA_WAIT1  asm volatile("cp.async.wait_group 1;" ::: "memory")
#define CPA_WAIT0  asm volatile("cp.async.wait_group 0;" ::: "memory")

// ================= unified tensor-core GEMM (merged hi/lo, cp.async 2-stage) =================
// C = Ah*Bh^T + Ah*Bl^T + Al*Bh^T (+bias) * outScale
// A row gr: (gr/rpc)*csA + (gr%rpc)*rsA ; z offsets: (z>>2)*q + (z&3)*r
template<int NB>
__global__ __launch_bounds__(256)
void tc_gemm(int Kd, int rpc, ll rsA, ll csA,
             const __nv_bfloat16* __restrict__ Ah, const __nv_bfloat16* __restrict__ Al,
             ll aZq, ll aZr,
             const __nv_bfloat16* __restrict__ Bh, const __nv_bfloat16* __restrict__ Bl,
             int ldB, ll bZq, ll bZr,
             const float* __restrict__ bias,
             float* __restrict__ Cf, __nv_bfloat16* __restrict__ Chi, __nv_bfloat16* __restrict__ Clo,
             int ldC, ll cZq, ll cZr, float outScale)
{
    constexpr int MW = (NB == 128) ? 4 : 2;
    constexpr int WM = (NB == 128) ? 2 : 4;
    constexpr int AE = 128 * 40;              // elems per A buffer
    constexpr int BE = NB * 40;
    constexpr int STAGE = 2 * AE + 2 * BE;    // elems per stage

    extern __shared__ __align__(16) __nv_bfloat16 dyn[];

    const int tid = threadIdx.x, wid = tid >> 5, lane = tid & 31;
    const int wm = wid % WM, wn = wid / WM;
    const int z = blockIdx.z;
    const int rowBase = blockIdx.y * 128, colBase = blockIdx.x * NB;
    const ll zA = (ll)(z >> 2) * aZq + (ll)(z & 3) * aZr;
    const ll zB = (ll)(z >> 2) * bZq + (ll)(z & 3) * bZr;
    const ll zC = (ll)(z >> 2) * cZq + (ll)(z & 3) * cZr;

    const __nv_bfloat16* pAh = Ah + zA;
    const __nv_bfloat16* pAl = Al + zA;
    const __nv_bfloat16* pBh = Bh + zB;
    const __nv_bfloat16* pBl = Bl + zB;
    const int T = Kd >> 5;

    // per-thread load coords
    const int arow = tid >> 2, ach = tid & 3;                 // + p*64 rows
    const ll aoffBase0 = (ll)((rowBase + arow) / rpc) * csA + (ll)((rowBase + arow) % rpc) * rsA;
    const ll aoffBase1 = (ll)((rowBase + arow + 64) / rpc) * csA + (ll)((rowBase + arow + 64) % rpc) * rsA;

    float acc[MW][4][4];
    #pragma unroll
    for (int i = 0; i < MW; i++)
        #pragma unroll
        for (int j = 0; j < 4; j++)
            #pragma unroll
            for (int c = 0; c < 4; c++) acc[i][j][c] = 0.f;

    const int aRowSel = ((lane >> 3) & 1) * 8 + (lane & 7);
    const int aKSel   = (lane >> 4) * 8;
    const int bRowSel = (lane >> 4) * 8 + (lane & 7);
    const int bKSel   = ((lane >> 3) & 1) * 8;

    auto issue = [&](int kt, int stg) {
        __nv_bfloat16* base = dyn + stg * STAGE;
        __nv_bfloat16* dAh = base;
        __nv_bfloat16* dAl = base + AE;
        __nv_bfloat16* dBh = base + 2 * AE;
        __nv_bfloat16* dBl = base + 2 * AE + BE;
        const int kc = kt * 32 + ach * 8;
        // A: 128 rows, thread covers rows arow and arow+64
        cpa16(su32(dAh + arow * 40 + ach * 8),        pAh + aoffBase0 + kc);
        cpa16(su32(dAl + arow * 40 + ach * 8),        pAl + aoffBase0 + kc);
        cpa16(su32(dAh + (arow + 64) * 40 + ach * 8), pAh + aoffBase1 + kc);
        cpa16(su32(dAl + (arow + 64) * 40 + ach * 8), pAl + aoffBase1 + kc);
        // B: NB rows
        #pragma unroll
        for (int p = 0; p < NB / 64; p++) {
            int r = arow + p * 64;
            ll off = (ll)(colBase + r) * ldB + kc;
            cpa16(su32(dBh + r * 40 + ach * 8), pBh + off);
            cpa16(su32(dBl + r * 40 + ach * 8), pBl + off);
        }
    };

    issue(0, 0); CPA_COMMIT;

    for (int t = 0; t < T; t++) {
        if (t + 1 < T) { issue(t + 1, (t + 1) & 1); CPA_COMMIT; CPA_WAIT1; }
        else           { CPA_WAIT0; }
        __syncthreads();

        const __nv_bfloat16* base = dyn + (t & 1) * STAGE;
        const u32 sAh = su32(base);
        const u32 sAl = sAh + AE * 2;           // bytes
        const u32 sBh = sAh + 2 * AE * 2;
        const u32 sBl = sAh + (2 * AE + BE) * 2;

        #pragma unroll
        for (int ks = 0; ks < 2; ks++) {
            u32 aH[MW][4], aL[MW][4], bH[4][2], bL[4][2];
            #pragma unroll
            for (int mi = 0; mi < MW; mi++) {
                int row = wm * (MW * 16) + mi * 16 + aRowSel;
                int kc = ks * 16 + aKSel;
                u32 boff = (row * 40 + kc) * 2;
                ldsm4(aH[mi][0], aH[mi][1], aH[mi][2], aH[mi][3], sAh + boff);
                ldsm4(aL[mi][0], aL[mi][1], aL[mi][2], aL[mi][3], sAl + boff);
            }
            #pragma unroll
            for (int np = 0; np < 2; np++) {
                int rowN = wn * 32 + np * 16 + bRowSel;
                int kc = ks * 16 + bKSel;
                u32 boff = (rowN * 40 + kc) * 2;
                ldsm4(bH[2*np][0], bH[2*np][1], bH[2*np+1][0], bH[2*np+1][1], sBh + boff);
                ldsm4(bL[2*np][0], bL[2*np][1], bL[2*np+1][0], bL[2*np+1][1], sBl + boff);
            }
            #pragma unroll
            for (int mi = 0; mi < MW; mi++)
                #pragma unroll
                for (int ni = 0; ni < 4; ni++) {
                    mma16816(acc[mi][ni], aH[mi], bH[ni]);
                    mma16816(acc[mi][ni], aH[mi], bL[ni]);
                    mma16816(acc[mi][ni], aL[mi], bH[ni]);
                }
        }
        __syncthreads();
    }

    // ---------------- epilogue ----------------
    const int gID = lane >> 2, tig = lane & 3;
    #pragma unroll
    for (int mi = 0; mi < MW; mi++) {
        #pragma unroll
        for (int ni = 0; ni < 4; ni++) {
            int gr0 = rowBase + wm * (MW * 16) + mi * 16 + gID;
            int gc  = colBase + wn * 32 + ni * 8 + tig * 2;
            float b0v = 0.f, b1v = 0.f;
            if (bias) { b0v = bias[gc]; b1v = bias[gc + 1]; }
            #pragma unroll
            for (int hrow = 0; hrow < 2; hrow++) {
                int gr = gr0 + hrow * 8;
                float v0 = acc[mi][ni][hrow*2+0] * outScale + b0v;
                float v1 = acc[mi][ni][hrow*2+1] * outScale + b1v;
                if (Cf) {
                    float2 o = {v0, v1};
                    *(float2*)(Cf + zC + (ll)gr * ldC + gc) = o;
                }
                if (Chi) {
                    __nv_bfloat16 h0 = __float2bfloat16(v0), h1 = __float2bfloat16(v1);
                    __nv_bfloat162 hp; hp.x = h0; hp.y = h1;
                    __nv_bfloat162 lp;
                    lp.x = __float2bfloat16(v0 - __bfloat162float(h0));
                    lp.y = __float2bfloat16(v1 - __bfloat162float(h1));
                    *(u32*)(Chi + zC + (ll)gr * ldC + gc) = *(u32*)&hp;
                    *(u32*)(Clo + zC + (ll)gr * ldC + gc) = *(u32*)&lp;
                }
            }
        }
    }
}

// ================= converts =================
__global__ void split_kernel(const float* __restrict__ in,
                             __nv_bfloat16* __restrict__ oh, __nv_bfloat16* __restrict__ ol, ll n)
{
    ll i = (ll)blockIdx.x * 256 + threadIdx.x;
    if (i >= n) return;
    float v = in[i];
    __nv_bfloat16 h = __float2bfloat16(v);
    oh[i] = h;
    ol[i] = __float2bfloat16(v - __bfloat162float(h));
}

__global__ void transpose_split(const float* __restrict__ W, ll zIn,
                                __nv_bfloat16* __restrict__ oh, __nv_bfloat16* __restrict__ ol, ll zOut,
                                int K, int N)
{
    __shared__ float tile[32][33];
    const int z = blockIdx.z;
    const float* in = W + (ll)z * zIn;
    const int n0 = blockIdx.x * 32, k0 = blockIdx.y * 32;
    const int tx = threadIdx.x, ty = threadIdx.y;
    #pragma unroll
    for (int i = 0; i < 32; i += 8)
        tile[ty + i][tx] = in[(ll)(k0 + ty + i) * N + n0 + tx];
    __syncthreads();
    #pragma unroll
    for (int i = 0; i < 32; i += 8) {
        float v = tile[tx][ty + i];
        ll o = (ll)z * zOut + (ll)(n0 + ty + i) * K + k0 + tx;
        __nv_bfloat16 h = __float2bfloat16(v);
        oh[o] = h;
        ol[o] = __float2bfloat16(v - __bfloat162float(h));
    }
}

__global__ void vtrans_kernel(const __nv_bfloat16* __restrict__ qh, const __nv_bfloat16* __restrict__ ql,
                              __nv_bfloat16* __restrict__ vh, __nv_bfloat16* __restrict__ vl, int L)
{
    __shared__ __nv_bfloat16 t0[32][33], t1[32][33];
    const int bh = blockIdx.z, b = bh >> 2, h = bh & 3;
    const int k0 = blockIdx.x * 32, c0 = blockIdx.y * 32;
    const int tx = threadIdx.x, ty = threadIdx.y;
    const __nv_bfloat16* s0 = qh + (ll)b * L * 768 + 512 + h * 64;
    const __nv_bfloat16* s1 = ql + (ll)b * L * 768 + 512 + h * 64;
    #pragma unroll
    for (int i = 0; i < 32; i += 8) {
        t0[ty + i][tx] = s0[(ll)(k0 + ty + i) * 768 + c0 + tx];
        t1[ty + i][tx] = s1[(ll)(k0 + ty + i) * 768 + c0 + tx];
    }
    __syncthreads();
    const ll ob = (ll)bh * 64 * L;
    #pragma unroll
    for (int i = 0; i < 32; i += 8) {
        ll o = ob + (ll)(c0 + ty + i) * L + k0 + tx;
        vh[o] = t0[tx][ty + i];
        vl[o] = t1[tx][ty + i];
    }
}

// ================= softmax =================
__global__ void softmax_w0_kernel(const float* __restrict__ SC,
                                  __nv_bfloat16* __restrict__ Ph, __nv_bfloat16* __restrict__ Pl,
                                  float* __restrict__ w0)
{
    const int b = blockIdx.x >> 11, q = blockIdx.x & 2047, tid = threadIdx.x;
    __shared__ float red[8];
    float wacc[8] = {0.f,0.f,0.f,0.f,0.f,0.f,0.f,0.f};

    #pragma unroll
    for (int h = 0; h < 4; h++) {
        const ll ro = ((ll)(b * 4 + h) * 2048 + q) * 2048;
        const float* p = SC + ro;
        float4 u0 = ((const float4*)p)[tid];
        float4 u1 = ((const float4*)p)[tid + 256];
        float v[8] = {u0.x,u0.y,u0.z,u0.w,u1.x,u1.y,u1.z,u1.w};
        float m = v[0];
        #pragma unroll
        for (int i = 1; i < 8; i++) m = fmaxf(m, v[i]);
        #pragma unroll
        for (int o = 16; o; o >>= 1) m = fmaxf(m, __shfl_xor_sync(0xffffffffu, m, o));
        if ((tid & 31) == 0) red[tid >> 5] = m;
        __syncthreads();
        float mt = red[0];
        #pragma unroll
        for (int k = 1; k < 8; k++) mt = fmaxf(mt, red[k]);
        __syncthreads();
        float s = 0.f;
        #pragma unroll
        for (int i = 0; i < 8; i++) { v[i] = __expf(v[i] - mt); s += v[i]; }
        #pragma unroll
        for (int o = 16; o; o >>= 1) s += __shfl_xor_sync(0xffffffffu, s, o);
        if ((tid & 31) == 0) red[tid >> 5] = s;
        __syncthreads();
        float st = 0.f;
        #pragma unroll
        for (int k = 0; k < 8; k++) st += red[k];
        __syncthreads();
        const float inv = 1.f / st;
        #pragma unroll
        for (int i = 0; i < 8; i++) { v[i] *= inv; wacc[i] += v[i]; }
        u32 hp[4], lp[4];
        #pragma unroll
        for (int j = 0; j < 4; j++) {
            float a = v[j*2], c = v[j*2+1];
            __nv_bfloat16 ha = __float2bfloat16(a), hc = __float2bfloat16(c);
            __nv_bfloat162 hh; hh.x = ha; hh.y = hc;
            __nv_bfloat162 lo; lo.x = __float2bfloat16(a - __bfloat162float(ha));
            lo.y = __float2bfloat16(c - __bfloat162float(hc));
            hp[j] = *(u32*)&hh; lp[j] = *(u32*)&lo;
        }
        uint2 h0 = {hp[0], hp[1]}, h1 = {hp[2], hp[3]};
        uint2 l0 = {lp[0], lp[1]}, l1 = {lp[2], lp[3]};
        ((uint2*)(Ph + ro))[tid] = h0;        ((uint2*)(Pl + ro))[tid] = l0;
        ((uint2*)(Ph + ro))[tid + 256] = h1;  ((uint2*)(Pl + ro))[tid + 256] = l1;
    }
    float* wr = w0 + ((ll)b * 2048 + q) * 2048;
    float4 o0 = {wacc[0]*0.25f, wacc[1]*0.25f, wacc[2]*0.25f, wacc[3]*0.25f};
    float4 o1 = {wacc[4]*0.25f, wacc[5]*0.25f, wacc[6]*0.25f, wacc[7]*0.25f};
    ((float4*)wr)[tid] = o0;
    ((float4*)wr)[tid + 256] = o1;
}

__global__ void softmax_bf16_kernel(const float* __restrict__ SC,
                                    __nv_bfloat16* __restrict__ Ph, __nv_bfloat16* __restrict__ Pl, int L)
{
    const ll row = blockIdx.x;
    const float* p = SC + row * (ll)L;
    const int tid = threadIdx.x;
    const int per = L >> 8;
    float v[4];
    float m = -1e30f;
    for (int i = 0; i < per; i++) { v[i] = p[tid + i * 256]; m = fmaxf(m, v[i]); }
    __shared__ float red[8];
    #pragma unroll
    for (int o = 16; o; o >>= 1) m = fmaxf(m, __shfl_xor_sync(0xffffffffu, m, o));
    if ((tid & 31) == 0) red[tid >> 5] = m;
    __syncthreads();
    float mt = red[0];
    #pragma unroll
    for (int k = 1; k < 8; k++) mt = fmaxf(mt, red[k]);
    __syncthreads();
    float s = 0.f;
    for (int i = 0; i < per; i++) { v[i] = __expf(v[i] - mt); s += v[i]; }
    #pragma unroll
    for (int o = 16; o; o >>= 1) s += __shfl_xor_sync(0xffffffffu, s, o);
    if ((tid & 31) == 0) red[tid >> 5] = s;
    __syncthreads();
    float st = 0.f;
    #pragma unroll
    for (int k = 0; k < 8; k++) st += red[k];
    const float inv = 1.f / st;
    for (int i = 0; i < per; i++) {
        float val = v[i] * inv;
        __nv_bfloat16 h = __float2bfloat16(val);
        Ph[row * (ll)L + tid + i * 256] = h;
        Pl[row * (ll)L + tid + i * 256] = __float2bfloat16(val - __bfloat162float(h));
    }
}

// ================= upsample + concat -> Z hi/lo =================
__global__ void upsample_kernel(const float* __restrict__ Y,
                                __nv_bfloat16* __restrict__ Zh, __nv_bfloat16* __restrict__ Zl)
{
    ll idx = (ll)blockIdx.x * 256 + threadIdx.x;
    int c = (int)(idx & (DMODEL - 1));
    ll bt = idx >> 10;
    int t = (int)(bt & (SEQ - 1));
    int b = (int)(bt >> 11);
    int i = c >> 8;
    int cc = c & 255;
    int L = SEQ >> i;
    int k = t >> i;
    int j = t & ((1 << i) - 1);
    float alpha = (float)j / (float)(1 << i);
    const int yrowoff[4] = {0, BATCH*SEQ, BATCH*SEQ + BATCH*SEQ/2,
                            BATCH*SEQ + BATCH*SEQ/2 + BATCH*SEQ/4};
    ll base = ((ll)yrowoff[i] + (ll)b * L + k) * EE + cc;
    float v = Y[base];
    float vn = (k + 1 < L) ? Y[base + EE] : 0.f;
    float z = (1.f - alpha) * v + alpha * vn;
    __nv_bfloat16 h = __float2bfloat16(z);
    Zh[idx] = h;
    Zl[idx] = __float2bfloat16(z - __bfloat162float(h));
}

// ================= layernorm =================
__global__ void layernorm_kernel(const float* __restrict__ Zf,
                                 const float* __restrict__ gam, const float* __restrict__ bet,
                                 float* __restrict__ out)
{
    const ll row = blockIdx.x;
    const float* p = Zf + row * DMODEL;
    const int tid = threadIdx.x;
    float v[4];
    float s = 0.f, s2 = 0.f;
    #pragma unroll
    for (int i = 0; i < 4; i++) { v[i] = p[tid + i * 256]; s += v[i]; s2 += v[i] * v[i]; }
    __shared__ float rs[8], rs2[8];
    #pragma unroll
    for (int o = 16; o; o >>= 1) { s += __shfl_xor_sync(0xffffffffu, s, o);
                                   s2 += __shfl_xor_sync(0xffffffffu, s2, o); }
    if ((tid & 31) == 0) { rs[tid >> 5] = s; rs2[tid >> 5] = s2; }
    __syncthreads();
    float ts = 0.f, ts2 = 0.f;
    #pragma unroll
    for (int k = 0; k < 8; k++) { ts += rs[k]; ts2 += rs2[k]; }
    const float mu = ts * (1.f / DMODEL);
    const float var = ts2 * (1.f / DMODEL) - mu * mu;
    const float inv = rsqrtf(var + 1e-5f);
    #pragma unroll
    for (int i = 0; i < 4; i++) {
        int c = tid + i * 256;
        out[row * DMODEL + c] = (v[i] - mu) * inv * gam[c] + bet[c];
    }
}

// ================= launch =================
extern "C" void kernel_launch(void* const* d_in, const int* in_sizes, int n_in,
                              void* d_out, int out_size)
{
    (void)in_sizes; (void)n_in; (void)out_size;
    const float* x     = (const float*)d_in[0];
    const float* projW = (const float*)d_in[1];
    const float* projb = (const float*)d_in[2];
    const float* inW   = (const float*)d_in[3];
    const float* inb   = (const float*)d_in[4];
    const float* outW  = (const float*)d_in[5];
    const float* outb  = (const float*)d_in[6];
    const float* fusW  = (const float*)d_in[7];
    const float* fusb  = (const float*)d_in[8];
    const float* lng   = (const float*)d_in[9];
    const float* lnb   = (const float*)d_in[10];

    float* fused = (float*)d_out;
    float* w0 = fused + (ll)BATCH * SEQ * DMODEL;

    __nv_bfloat16 *xh,*xl,*PWth,*PWtl,*IWth,*IWtl,*OWth,*OWtl,*FWth,*FWtl;
    __nv_bfloat16 *Xsh,*Xsl,*Qh,*Ql,*Vth,*Vtl,*Ph,*Pl,*Oh,*Ol,*Zh,*Zl;
    float *SC,*Y,*ZF;
    cudaGetSymbolAddress((void**)&xh, g_xh);   cudaGetSymbolAddress((void**)&xl, g_xl);
    cudaGetSymbolAddress((void**)&PWth, g_PWth); cudaGetSymbolAddress((void**)&PWtl, g_PWtl);
    cudaGetSymbolAddress((void**)&IWth, g_IWth); cudaGetSymbolAddress((void**)&IWtl, g_IWtl);
    cudaGetSymbolAddress((void**)&OWth, g_OWth); cudaGetSymbolAddress((void**)&OWtl, g_OWtl);
    cudaGetSymbolAddress((void**)&FWth, g_FWth); cudaGetSymbolAddress((void**)&FWtl, g_FWtl);
    cudaGetSymbolAddress((void**)&Xsh, g_Xsh); cudaGetSymbolAddress((void**)&Xsl, g_Xsl);
    cudaGetSymbolAddress((void**)&Qh, g_Qh);   cudaGetSymbolAddress((void**)&Ql, g_Ql);
    cudaGetSymbolAddress((void**)&Vth, g_Vth); cudaGetSymbolAddress((void**)&Vtl, g_Vtl);
    cudaGetSymbolAddress((void**)&Ph, g_Ph);   cudaGetSymbolAddress((void**)&Pl, g_Pl);
    cudaGetSymbolAddress((void**)&Oh, g_Oh);   cudaGetSymbolAddress((void**)&Ol, g_Ol);
    cudaGetSymbolAddress((void**)&Zh, g_Zh);   cudaGetSymbolAddress((void**)&Zl, g_Zl);
    cudaGetSymbolAddress((void**)&SC, g_SC);
    cudaGetSymbolAddress((void**)&Y, g_Y);
    cudaGetSymbolAddress((void**)&ZF, g_ZF);

    const dim3 blk(256);
    const dim3 tblk(32, 8);

    // dynamic smem: 2 stages * (2*128*40 + 2*NB*40) bf16
    const int smem128 = 2 * (2 * 128 * 40 + 2 * 128 * 40) * 2;   // 81920
    const int smem64  = 2 * (2 * 128 * 40 + 2 * 64 * 40) * 2;    // 61440
    static int attrSet = 0;
    cudaFuncSetAttribute(tc_gemm<128>, cudaFuncAttributeMaxDynamicSharedMemorySize, smem128);
    cudaFuncSetAttribute(tc_gemm<64>,  cudaFuncAttributeMaxDynamicSharedMemorySize, smem64);
    (void)attrSet;

    split_kernel<<<(unsigned)(((ll)BATCH*SEQ*DMODEL + 255) / 256), blk>>>(x, xh, xl, (ll)BATCH*SEQ*DMODEL);
    transpose_split<<<dim3(EE/32, DMODEL/32, NSC), tblk>>>(projW, (ll)DMODEL*EE, PWth, PWtl, (ll)EE*DMODEL, DMODEL, EE);
    transpose_split<<<dim3(768/32, EE/32, NSC), tblk>>>(inW, (ll)EE*768, IWth, IWtl, (ll)768*EE, EE, 768);
    transpose_split<<<dim3(EE/32, EE/32, NSC), tblk>>>(outW, (ll)EE*EE, OWth, OWtl, (ll)EE*EE, EE, EE);
    transpose_split<<<dim3(DMODEL/32, DMODEL/32, 1), tblk>>>(fusW, 0, FWth, FWtl, 0, DMODEL, DMODEL);

    int yoff = 0;
    for (int i = 0; i < NSC; i++) {
        const int s = 1 << i;
        const int L = SEQ >> i;
        const int rows = BATCH * L;
        const ll LL = (ll)L * L;

        // proj: (rows,1024)@(1024,256) -> Xs hi/lo
        tc_gemm<128><<<dim3(EE/128, rows/128, 1), blk, smem128>>>(
            DMODEL, L, (ll)s * DMODEL, (ll)SEQ * DMODEL,
            xh, xl, 0, 0,
            PWth + (ll)i*EE*DMODEL, PWtl + (ll)i*EE*DMODEL, DMODEL, 0, 0,
            projb + i * EE, nullptr, Xsh, Xsl, EE, 0, 0, 1.f);

        // qkv: (rows,256)@(256,768) -> Q hi/lo
        tc_gemm<128><<<dim3(768/128, rows/128, 1), blk, smem128>>>(
            EE, rows, (ll)EE, 0,
            Xsh, Xsl, 0, 0,
            IWth + (ll)i*768*EE, IWtl + (ll)i*768*EE, EE, 0, 0,
            inb + i * 768, nullptr, Qh, Ql, 768, 0, 0, 1.f);

        // V transpose
        vtrans_kernel<<<dim3(L/32, 2, 16), tblk>>>(Qh, Ql, Vth, Vtl, L);

        // scores: per bh, (L,64)@(L,64)^T -> SC fp32, scale 0.125
        tc_gemm<128><<<dim3(L/128, L/128, 16), blk, smem128>>>(
            64, L, 768, 0,
            Qh, Ql, (ll)L * 768, 64,
            Qh + 256, Ql + 256, 768, (ll)L * 768, 64,
            nullptr, SC, nullptr, nullptr, L, 4 * LL, LL, 0.125f);

        // softmax
        if (i == 0)
            softmax_w0_kernel<<<BATCH * SEQ, blk>>>(SC, Ph, Pl, w0);
        else
            softmax_bf16_kernel<<<BATCH * 4 * L, blk>>>(SC, Ph, Pl, L);

        // PV: per bh, (L,L)@(64,L)^T -> O hi/lo (col block h*64)
        tc_gemm<64><<<dim3(1, L/128, 16), blk, smem64>>>(
            L, L, (ll)L, 0,
            Ph, Pl, 4 * LL, LL,
            Vth, Vtl, L, (ll)256 * L, (ll)64 * L,
            nullptr, nullptr, Oh, Ol, EE, (ll)L * EE, 64, 1.f);

        // out proj: (rows,256)@(256,256) -> Y fp32
        tc_gemm<128><<<dim3(EE/128, rows/128, 1), blk, smem128>>>(
            EE, rows, (ll)EE, 0,
            Oh, Ol, 0, 0,
            OWth + (ll)i*EE*EE, OWtl + (ll)i*EE*EE, EE, 0, 0,
            outb + i * EE, Y + (ll)yoff * EE, nullptr, nullptr, EE, 0, 0, 1.f);

        yoff += rows;
    }

    // upsample + concat -> Z hi/lo
    upsample_kernel<<<(unsigned)(((ll)BATCH*SEQ*DMODEL) / 256), blk>>>(Y, Zh, Zl);

    // fusion: (8192,1024)@(1024,1024) -> ZF fp32
    tc_gemm<128><<<dim3(DMODEL/128, (BATCH*SEQ)/128, 1), blk, smem128>>>(
        DMODEL, BATCH * SEQ, (ll)DMODEL, 0,
        Zh, Zl, 0, 0,
        FWth, FWtl, DMODEL, 0, 0,
        fusb, ZF, nullptr, nullptr, DMODEL, 0, 0, 1.f);

    // layernorm -> fused output
    layernorm_kernel<<<BATCH * SEQ, blk>>>(ZF, lng, lnb, fused);
}

// round 6
// speedup vs baseline: 2.2444x; 1.0035x over previous
#include <cuda_runtime.h>
#include <cuda_bf16.h>
#include <cstdint>

typedef long long ll;
typedef unsigned int u32;
typedef unsigned long long u64;

#define BATCH 4
#define SEQ   2048
#define DMODEL 1024
#define EE    256
#define NSC   4

// ================= static device scratch =================
__device__ __nv_bfloat16 g_xh [BATCH*SEQ*DMODEL], g_xl [BATCH*SEQ*DMODEL];
__device__ __nv_bfloat16 g_PWth[NSC*EE*DMODEL],   g_PWtl[NSC*EE*DMODEL];
__device__ __nv_bfloat16 g_IWth[NSC*768*EE],      g_IWtl[NSC*768*EE];
__device__ __nv_bfloat16 g_OWth[NSC*EE*EE],       g_OWtl[NSC*EE*EE];
__device__ __nv_bfloat16 g_FWth[DMODEL*DMODEL],   g_FWtl[DMODEL*DMODEL];
__device__ __nv_bfloat16 g_Xsh[BATCH*SEQ*EE],     g_Xsl[BATCH*SEQ*EE];
__device__ __nv_bfloat16 g_Qh [BATCH*SEQ*768],    g_Ql [BATCH*SEQ*768];
__device__ __nv_bfloat16 g_Vth[16*64*SEQ],        g_Vtl[16*64*SEQ];
__device__ __nv_bfloat16 g_Sh [16ull*SEQ*SEQ],    g_Sl [16ull*SEQ*SEQ];  // scale-0 score export
__device__ float         g_M  [16*SEQ],           g_IL [16*SEQ];
__device__ __nv_bfloat16 g_Oh [BATCH*SEQ*EE],     g_Ol [BATCH*SEQ*EE];
__device__ float         g_Y  [(BATCH*(SEQ+SEQ/2+SEQ/4+SEQ/8))*EE];
__device__ __nv_bfloat16 g_Zh [BATCH*SEQ*DMODEL], g_Zl [BATCH*SEQ*DMODEL];
__device__ float         g_ZF [BATCH*SEQ*DMODEL];

// ================= PTX helpers =================
__device__ __forceinline__ u32 su32(const void* p) {
    u32 a; asm("{ .reg .u64 t; cvta.to.shared.u64 t,%1; cvt.u32.u64 %0,t; }" : "=r"(a) : "l"(p));
    return a;
}
__device__ __forceinline__ void ldsm4(u32& r0, u32& r1, u32& r2, u32& r3, u32 addr) {
    asm volatile("ldmatrix.sync.aligned.m8n8.x4.shared.b16 {%0,%1,%2,%3},[%4];"
                 : "=r"(r0), "=r"(r1), "=r"(r2), "=r"(r3) : "r"(addr));
}
__device__ __forceinline__ void mma16816(float* c, const u32* a, const u32* b) {
    asm volatile("mma.sync.aligned.m16n8k16.row.col.f32.bf16.bf16.f32 "
                 "{%0,%1,%2,%3},{%4,%5,%6,%7},{%8,%9},{%0,%1,%2,%3};"
                 : "+f"(c[0]), "+f"(c[1]), "+f"(c[2]), "+f"(c[3])
                 : "r"(a[0]), "r"(a[1]), "r"(a[2]), "r"(a[3]), "r"(b[0]), "r"(b[1]));
}
__device__ __forceinline__ void cpa16(u32 saddr, const void* g) {
    asm volatile("cp.async.cg.shared.global [%0],[%1],16;" :: "r"(saddr), "l"(g));
}
#define CPA_COMMIT asm volatile("cp.async.commit_group;" ::: "memory")
#define CPA_WAIT1  asm volatile("cp.async.wait_group 1;" ::: "memory")
#define CPA_WAIT0  asm volatile("cp.async.wait_group 0;" ::: "memory")

__device__ __forceinline__ void bfsplit2(float v0, float v1, u32& hi, u32& lo) {
    __nv_bfloat162 h; h.x = __float2bfloat16(v0); h.y = __float2bfloat16(v1);
    __nv_bfloat162 l; l.x = __float2bfloat16(v0 - __bfloat162float(h.x));
    l.y = __float2bfloat16(v1 - __bfloat162float(h.y));
    hi = *(u32*)&h; lo = *(u32*)&l;
}

// ================= unified tensor-core GEMM (merged hi/lo, cp.async 2-stage) =================
template<int NB>
__global__ __launch_bounds__(256)
void tc_gemm(int Kd, int rpc, ll rsA, ll csA,
             const __nv_bfloat16* __restrict__ Ah, const __nv_bfloat16* __restrict__ Al,
             ll aZq, ll aZr,
             const __nv_bfloat16* __restrict__ Bh, const __nv_bfloat16* __restrict__ Bl,
             int ldB, ll bZq, ll bZr,
             const float* __restrict__ bias,
             float* __restrict__ Cf, __nv_bfloat16* __restrict__ Chi, __nv_bfloat16* __restrict__ Clo,
             int ldC, ll cZq, ll cZr, float outScale)
{
    constexpr int MW = (NB == 128) ? 4 : 2;
    constexpr int WM = (NB == 128) ? 2 : 4;
    constexpr int AE = 128 * 40;
    constexpr int BE = NB * 40;
    constexpr int STAGE = 2 * AE + 2 * BE;

    extern __shared__ __align__(16) __nv_bfloat16 dyn[];

    const int tid = threadIdx.x, wid = tid >> 5, lane = tid & 31;
    const int wm = wid % WM, wn = wid / WM;
    const int z = blockIdx.z;
    const int rowBase = blockIdx.y * 128, colBase = blockIdx.x * NB;
    const ll zA = (ll)(z >> 2) * aZq + (ll)(z & 3) * aZr;
    const ll zB = (ll)(z >> 2) * bZq + (ll)(z & 3) * bZr;
    const ll zC = (ll)(z >> 2) * cZq + (ll)(z & 3) * cZr;

    const __nv_bfloat16* pAh = Ah + zA;
    const __nv_bfloat16* pAl = Al + zA;
    const __nv_bfloat16* pBh = Bh + zB;
    const __nv_bfloat16* pBl = Bl + zB;
    const int T = Kd >> 5;

    const int arow = tid >> 2, ach = tid & 3;
    const ll aoffBase0 = (ll)((rowBase + arow) / rpc) * csA + (ll)((rowBase + arow) % rpc) * rsA;
    const ll aoffBase1 = (ll)((rowBase + arow + 64) / rpc) * csA + (ll)((rowBase + arow + 64) % rpc) * rsA;

    float acc[MW][4][4];
    #pragma unroll
    for (int i = 0; i < MW; i++)
        #pragma unroll
        for (int j = 0; j < 4; j++)
            #pragma unroll
            for (int c = 0; c < 4; c++) acc[i][j][c] = 0.f;

    const int aRowSel = ((lane >> 3) & 1) * 8 + (lane & 7);
    const int aKSel   = (lane >> 4) * 8;
    const int bRowSel = (lane >> 4) * 8 + (lane & 7);
    const int bKSel   = ((lane >> 3) & 1) * 8;

    auto issue = [&](int kt, int stg) {
        __nv_bfloat16* base = dyn + stg * STAGE;
        __nv_bfloat16* dAh = base;
        __nv_bfloat16* dAl = base + AE;
        __nv_bfloat16* dBh = base + 2 * AE;
        __nv_bfloat16* dBl = base + 2 * AE + BE;
        const int kc = kt * 32 + ach * 8;
        cpa16(su32(dAh + arow * 40 + ach * 8),        pAh + aoffBase0 + kc);
        cpa16(su32(dAl + arow * 40 + ach * 8),        pAl + aoffBase0 + kc);
        cpa16(su32(dAh + (arow + 64) * 40 + ach * 8), pAh + aoffBase1 + kc);
        cpa16(su32(dAl + (arow + 64) * 40 + ach * 8), pAl + aoffBase1 + kc);
        #pragma unroll
        for (int p = 0; p < NB / 64; p++) {
            int r = arow + p * 64;
            ll off = (ll)(colBase + r) * ldB + kc;
            cpa16(su32(dBh + r * 40 + ach * 8), pBh + off);
            cpa16(su32(dBl + r * 40 + ach * 8), pBl + off);
        }
    };

    issue(0, 0); CPA_COMMIT;

    for (int t = 0; t < T; t++) {
        if (t + 1 < T) { issue(t + 1, (t + 1) & 1); CPA_COMMIT; CPA_WAIT1; }
        else           { CPA_WAIT0; }
        __syncthreads();

        const __nv_bfloat16* base = dyn + (t & 1) * STAGE;
        const u32 sAh = su32(base);
        const u32 sAl = sAh + AE * 2;
        const u32 sBh = sAh + 2 * AE * 2;
        const u32 sBl = sAh + (2 * AE + BE) * 2;

        #pragma unroll
        for (int ks = 0; ks < 2; ks++) {
            u32 aH[MW][4], aL[MW][4], bH[4][2], bL[4][2];
            #pragma unroll
            for (int mi = 0; mi < MW; mi++) {
                int row = wm * (MW * 16) + mi * 16 + aRowSel;
                int kc = ks * 16 + aKSel;
                u32 boff = (row * 40 + kc) * 2;
                ldsm4(aH[mi][0], aH[mi][1], aH[mi][2], aH[mi][3], sAh + boff);
                ldsm4(aL[mi][0], aL[mi][1], aL[mi][2], aL[mi][3], sAl + boff);
            }
            #pragma unroll
            for (int np = 0; np < 2; np++) {
                int rowN = wn * 32 + np * 16 + bRowSel;
                int kc = ks * 16 + bKSel;
                u32 boff = (rowN * 40 + kc) * 2;
                ldsm4(bH[2*np][0], bH[2*np][1], bH[2*np+1][0], bH[2*np+1][1], sBh + boff);
                ldsm4(bL[2*np][0], bL[2*np][1], bL[2*np+1][0], bL[2*np+1][1], sBl + boff);
            }
            #pragma unroll
            for (int mi = 0; mi < MW; mi++)
                #pragma unroll
                for (int ni = 0; ni < 4; ni++) {
                    mma16816(acc[mi][ni], aH[mi], bH[ni]);
                    mma16816(acc[mi][ni], aH[mi], bL[ni]);
                    mma16816(acc[mi][ni], aL[mi], bH[ni]);
                }
        }
        __syncthreads();
    }

    const int gID = lane >> 2, tig = lane & 3;
    #pragma unroll
    for (int mi = 0; mi < MW; mi++) {
        #pragma unroll
        for (int ni = 0; ni < 4; ni++) {
            int gr0 = rowBase + wm * (MW * 16) + mi * 16 + gID;
            int gc  = colBase + wn * 32 + ni * 8 + tig * 2;
            float b0v = 0.f, b1v = 0.f;
            if (bias) { b0v = bias[gc]; b1v = bias[gc + 1]; }
            #pragma unroll
            for (int hrow = 0; hrow < 2; hrow++) {
                int gr = gr0 + hrow * 8;
                float v0 = acc[mi][ni][hrow*2+0] * outScale + b0v;
                float v1 = acc[mi][ni][hrow*2+1] * outScale + b1v;
                if (Cf) {
                    float2 o = {v0, v1};
                    *(float2*)(Cf + zC + (ll)gr * ldC + gc) = o;
                }
                if (Chi) {
                    u32 hp, lp;
                    bfsplit2(v0, v1, hp, lp);
                    *(u32*)(Chi + zC + (ll)gr * ldC + gc) = hp;
                    *(u32*)(Clo + zC + (ll)gr * ldC + gc) = lp;
                }
            }
        }
    }
}

// ================= fused flash attention =================
// grid: (L/128, 16). 8 warps, warp w owns q-rows [qBase + w*16, +16).
// S = (Q K^T)*0.125 with 3-product hi/lo; online softmax; O = P V (3-product).
// WRITE_S: export scaled scores bf16 hi/lo + per-row m, 1/l (scale 0 only).
template<int WRITE_S>
__global__ __launch_bounds__(256)
void flash_kernel(int L,
    const __nv_bfloat16* __restrict__ qkvh, const __nv_bfloat16* __restrict__ qkvl,
    const __nv_bfloat16* __restrict__ Vh,   const __nv_bfloat16* __restrict__ Vl,
    __nv_bfloat16* __restrict__ Ohi, __nv_bfloat16* __restrict__ Olo,
    __nv_bfloat16* __restrict__ Shi, __nv_bfloat16* __restrict__ Slo,
    float* __restrict__ gM, float* __restrict__ gIL)
{
    extern __shared__ __align__(16) __nv_bfloat16 sm[];
    __nv_bfloat16* sQH = sm;
    __nv_bfloat16* sQL = sm + 9216;
    __nv_bfloat16* sKH = sm + 18432;
    __nv_bfloat16* sKL = sm + 27648;
    __nv_bfloat16* sVH = sm + 36864;
    __nv_bfloat16* sVL = sm + 45568;

    const int tid = threadIdx.x, wid = tid >> 5, lane = tid & 31;
    const int gid = lane >> 2, tig = lane & 3;
    const int bh = blockIdx.y, b = bh >> 2, h = bh & 3;
    const int qBase = blockIdx.x << 7;

    const ll qoff = (ll)b * L * 768 + h * 64;
    const ll koff = qoff + 256;
    const ll voff = (ll)bh * 64 * L;

    // load Q tile once
    #pragma unroll
    for (int p = 0; p < 4; p++) {
        int idx = tid + p * 256;
        int r = idx >> 3, c = (idx & 7) * 8;
        ll g = qoff + (ll)(qBase + r) * 768 + c;
        cpa16(su32(sQH + r * 72 + c), qkvh + g);
        cpa16(su32(sQL + r * 72 + c), qkvl + g);
    }
    CPA_COMMIT; CPA_WAIT0; __syncthreads();

    const int aRowSel = ((lane >> 3) & 1) * 8 + (lane & 7);
    const int aKSel   = (lane >> 4) * 8;
    const int bRowSel = (lane >> 4) * 8 + (lane & 7);
    const int bKSel   = ((lane >> 3) & 1) * 8;

    const u32 sQHa = su32(sQH), sQLa = su32(sQL);
    const u32 sKHa = su32(sKH), sKLa = su32(sKL);
    const u32 sVHa = su32(sVH), sVLa = su32(sVL);

    float m0 = -1e30f, m1 = -1e30f, l0 = 0.f, l1 = 0.f;
    float oacc[8][4];
    #pragma unroll
    for (int g = 0; g < 8; g++)
        #pragma unroll
        for (int c = 0; c < 4; c++) oacc[g][c] = 0.f;

    const int nT = L >> 7;
    for (int kt = 0; kt < nT; kt++) {
        // load K (128x64) and V (64x128) tiles hi/lo
        #pragma unroll
        for (int p = 0; p < 4; p++) {
            int idx = tid + p * 256;
            int r = idx >> 3, c = (idx & 7) * 8;
            ll g = koff + (ll)(kt * 128 + r) * 768 + c;
            cpa16(su32(sKH + r * 72 + c), qkvh + g);
            cpa16(su32(sKL + r * 72 + c), qkvl + g);
            int d = idx >> 4, c2 = (idx & 15) * 8;
            ll gv = voff + (ll)d * L + kt * 128 + c2;
            cpa16(su32(sVH + d * 136 + c2), Vh + gv);
            cpa16(su32(sVL + d * 136 + c2), Vl + gv);
        }
        CPA_COMMIT; CPA_WAIT0; __syncthreads();

        // ---- S = Q K^T ----
        float sacc[16][4];
        #pragma unroll
        for (int nf = 0; nf < 16; nf++)
            #pragma unroll
            for (int c = 0; c < 4; c++) sacc[nf][c] = 0.f;

        #pragma unroll
        for (int k16 = 0; k16 < 4; k16++) {
            u32 aH[4], aL[4];
            u32 ab = ((wid * 16 + aRowSel) * 72 + k16 * 16 + aKSel) * 2;
            ldsm4(aH[0], aH[1], aH[2], aH[3], sQHa + ab);
            ldsm4(aL[0], aL[1], aL[2], aL[3], sQLa + ab);
            #pragma unroll
            for (int g = 0; g < 8; g++) {
                u32 b0[2], b1[2], c0[2], c1[2];
                u32 bb = ((g * 16 + bRowSel) * 72 + k16 * 16 + bKSel) * 2;
                ldsm4(b0[0], b0[1], b1[0], b1[1], sKHa + bb);
                ldsm4(c0[0], c0[1], c1[0], c1[1], sKLa + bb);
                mma16816(sacc[2*g],   aH, b0); mma16816(sacc[2*g],   aH, c0); mma16816(sacc[2*g],   aL, b0);
                mma16816(sacc[2*g+1], aH, b1); mma16816(sacc[2*g+1], aH, c1); mma16816(sacc[2*g+1], aL, b1);
            }
        }
        #pragma unroll
        for (int nf = 0; nf < 16; nf++)
            #pragma unroll
            for (int c = 0; c < 4; c++) sacc[nf][c] *= 0.125f;

        if (WRITE_S) {
            int r0 = qBase + wid * 16 + gid;
            ll base0 = (ll)bh * L * L + (ll)r0 * L + kt * 128;
            ll base1 = base0 + 8LL * L;
            #pragma unroll
            for (int nf = 0; nf < 16; nf++) {
                int col = nf * 8 + tig * 2;
                u32 hp, lp;
                bfsplit2(sacc[nf][0], sacc[nf][1], hp, lp);
                *(u32*)(Shi + base0 + col) = hp;
                *(u32*)(Slo + base0 + col) = lp;
                bfsplit2(sacc[nf][2], sacc[nf][3], hp, lp);
                *(u32*)(Shi + base1 + col) = hp;
                *(u32*)(Slo + base1 + col) = lp;
            }
        }

        // ---- pass 1: row max ----
        float tm0 = -1e30f, tm1 = -1e30f;
        #pragma unroll
        for (int nf = 0; nf < 16; nf++) {
            tm0 = fmaxf(tm0, fmaxf(sacc[nf][0], sacc[nf][1]));
            tm1 = fmaxf(tm1, fmaxf(sacc[nf][2], sacc[nf][3]));
        }
        tm0 = fmaxf(tm0, __shfl_xor_sync(0xffffffffu, tm0, 1));
        tm0 = fmaxf(tm0, __shfl_xor_sync(0xffffffffu, tm0, 2));
        tm1 = fmaxf(tm1, __shfl_xor_sync(0xffffffffu, tm1, 1));
        tm1 = fmaxf(tm1, __shfl_xor_sync(0xffffffffu, tm1, 2));
        float M0 = fmaxf(m0, tm0), M1 = fmaxf(m1, tm1);
        float al0 = __expf(m0 - M0), al1 = __expf(m1 - M1);
        m0 = M0; m1 = M1;
        l0 *= al0; l1 *= al1;
        #pragma unroll
        for (int g = 0; g < 8; g++) {
            oacc[g][0] *= al0; oacc[g][1] *= al0;
            oacc[g][2] *= al1; oacc[g][3] *= al1;
        }

        // ---- pass 2: exp -> P frags -> P·V ----
        float s0 = 0.f, s1 = 0.f;
        #pragma unroll
        for (int j = 0; j < 8; j++) {
            float p0 = __expf(sacc[2*j][0]   - M0), p1 = __expf(sacc[2*j][1]   - M0);
            float p2 = __expf(sacc[2*j][2]   - M1), p3 = __expf(sacc[2*j][3]   - M1);
            float p4 = __expf(sacc[2*j+1][0] - M0), p5 = __expf(sacc[2*j+1][1] - M0);
            float p6 = __expf(sacc[2*j+1][2] - M1), p7 = __expf(sacc[2*j+1][3] - M1);
            s0 += p0 + p1 + p4 + p5;
            s1 += p2 + p3 + p6 + p7;
            u32 pH[4], pL[4];
            bfsplit2(p0, p1, pH[0], pL[0]);
            bfsplit2(p2, p3, pH[1], pL[1]);
            bfsplit2(p4, p5, pH[2], pL[2]);
            bfsplit2(p6, p7, pH[3], pL[3]);
            #pragma unroll
            for (int g = 0; g < 4; g++) {
                u32 b0[2], b1[2], c0[2], c1[2];
                u32 vb = ((g * 16 + bRowSel) * 136 + j * 16 + bKSel) * 2;
                ldsm4(b0[0], b0[1], b1[0], b1[1], sVHa + vb);
                ldsm4(c0[0], c0[1], c1[0], c1[1], sVLa + vb);
                mma16816(oacc[2*g],   pH, b0); mma16816(oacc[2*g],   pH, c0); mma16816(oacc[2*g],   pL, b0);
                mma16816(oacc[2*g+1], pH, b1); mma16816(oacc[2*g+1], pH, c1); mma16816(oacc[2*g+1], pL, b1);
            }
        }
        s0 += __shfl_xor_sync(0xffffffffu, s0, 1);
        s0 += __shfl_xor_sync(0xffffffffu, s0, 2);
        s1 += __shfl_xor_sync(0xffffffffu, s1, 1);
        s1 += __shfl_xor_sync(0xffffffffu, s1, 2);
        l0 += s0; l1 += s1;
        __syncthreads();
    }

    // ---- epilogue: O /= l, write bf16 hi/lo ----
    float inv0 = 1.f / l0, inv1 = 1.f / l1;
    int r0 = qBase + wid * 16 + gid;
    ll ob0 = (ll)b * L * 256 + (ll)r0 * 256 + h * 64;
    ll ob1 = ob0 + 8LL * 256;
    #pragma unroll
    for (int nf = 0; nf < 8; nf++) {
        int col = nf * 8 + tig * 2;
        u32 hp, lp;
        bfsplit2(oacc[nf][0] * inv0, oacc[nf][1] * inv0, hp, lp);
        *(u32*)(Ohi + ob0 + col) = hp;
        *(u32*)(Olo + ob0 + col) = lp;
        bfsplit2(oacc[nf][2] * inv1, oacc[nf][3] * inv1, hp, lp);
        *(u32*)(Ohi + ob1 + col) = hp;
        *(u32*)(Olo + ob1 + col) = lp;
    }
    if (WRITE_S && tig == 0) {
        gM[bh * L + r0]     = m0;
        gM[bh * L + r0 + 8] = m1;
        gIL[bh * L + r0]     = inv0;
        gIL[bh * L + r0 + 8] = inv1;
    }
}

// ================= w0 from exported scores =================
__global__ void w0_kernel(const __nv_bfloat16* __restrict__ Sh, const __nv_bfloat16* __restrict__ Sl,
                          const float* __restrict__ gM, const float* __restrict__ gIL,
                          float* __restrict__ w0)
{
    ll idx = (ll)blockIdx.x * 256 + threadIdx.x;   // over B*S*S
    int k = (int)(idx & 2047);
    int q = (int)((idx >> 11) & 2047);
    int b = (int)(idx >> 22);
    float acc = 0.f;
    #pragma unroll
    for (int h = 0; h < 4; h++) {
        int bh = b * 4 + h;
        ll off = (ll)bh * SEQ * SEQ + (ll)q * SEQ + k;
        float s = __bfloat162float(Sh[off]) + __bfloat162float(Sl[off]);
        acc += __expf(s - gM[bh * SEQ + q]) * gIL[bh * SEQ + q];
    }
    w0[idx] = 0.25f * acc;
}

// ================= converts =================
__global__ void split_kernel(const float* __restrict__ in,
                             __nv_bfloat16* __restrict__ oh, __nv_bfloat16* __restrict__ ol, ll n)
{
    ll i = (ll)blockIdx.x * 256 + threadIdx.x;
    if (i >= n) return;
    float v = in[i];
    __nv_bfloat16 h = __float2bfloat16(v);
    oh[i] = h;
    ol[i] = __float2bfloat16(v - __bfloat162float(h));
}

__global__ void transpose_split(const float* __restrict__ W, ll zIn,
                                __nv_bfloat16* __restrict__ oh, __nv_bfloat16* __restrict__ ol, ll zOut,
                                int K, int N)
{
    __shared__ float tile[32][33];
    const int z = blockIdx.z;
    const float* in = W + (ll)z * zIn;
    const int n0 = blockIdx.x * 32, k0 = blockIdx.y * 32;
    const int tx = threadIdx.x, ty = threadIdx.y;
    #pragma unroll
    for (int i = 0; i < 32; i += 8)
        tile[ty + i][tx] = in[(ll)(k0 + ty + i) * N + n0 + tx];
    __syncthreads();
    #pragma unroll
    for (int i = 0; i < 32; i += 8) {
        float v = tile[tx][ty + i];
        ll o = (ll)z * zOut + (ll)(n0 + ty + i) * K + k0 + tx;
        __nv_bfloat16 h = __float2bfloat16(v);
        oh[o] = h;
        ol[o] = __float2bfloat16(v - __bfloat162float(h));
    }
}

__global__ void vtrans_kernel(const __nv_bfloat16* __restrict__ qh, const __nv_bfloat16* __restrict__ ql,
                              __nv_bfloat16* __restrict__ vh, __nv_bfloat16* __restrict__ vl, int L)
{
    __shared__ __nv_bfloat16 t0[32][33], t1[32][33];
    const int bh = blockIdx.z, b = bh >> 2, h = bh & 3;
    const int k0 = blockIdx.x * 32, c0 = blockIdx.y * 32;
    const int tx = threadIdx.x, ty = threadIdx.y;
    const __nv_bfloat16* s0 = qh + (ll)b * L * 768 + 512 + h * 64;
    const __nv_bfloat16* s1 = ql + (ll)b * L * 768 + 512 + h * 64;
    #pragma unroll
    for (int i = 0; i < 32; i += 8) {
        t0[ty + i][tx] = s0[(ll)(k0 + ty + i) * 768 + c0 + tx];
        t1[ty + i][tx] = s1[(ll)(k0 + ty + i) * 768 + c0 + tx];
    }
    __syncthreads();
    const ll ob = (ll)bh * 64 * L;
    #pragma unroll
    for (int i = 0; i < 32; i += 8) {
        ll o = ob + (ll)(c0 + ty + i) * L + k0 + tx;
        vh[o] = t0[tx][ty + i];
        vl[o] = t1[tx][ty + i];
    }
}

// ================= upsample + concat -> Z hi/lo =================
__global__ void upsample_kernel(const float* __restrict__ Y,
                                __nv_bfloat16* __restrict__ Zh, __nv_bfloat16* __restrict__ Zl)
{
    ll idx = (ll)blockIdx.x * 256 + threadIdx.x;
    int c = (int)(idx & (DMODEL - 1));
    ll bt = idx >> 10;
    int t = (int)(bt & (SEQ - 1));
    int b = (int)(bt >> 11);
    int i = c >> 8;
    int cc = c & 255;
    int L = SEQ >> i;
    int k = t >> i;
    int j = t & ((1 << i) - 1);
    float alpha = (float)j / (float)(1 << i);
    const int yrowoff[4] = {0, BATCH*SEQ, BATCH*SEQ + BATCH*SEQ/2,
                            BATCH*SEQ + BATCH*SEQ/2 + BATCH*SEQ/4};
    ll base = ((ll)yrowoff[i] + (ll)b * L + k) * EE + cc;
    float v = Y[base];
    float vn = (k + 1 < L) ? Y[base + EE] : 0.f;
    float z = (1.f - alpha) * v + alpha * vn;
    __nv_bfloat16 h = __float2bfloat16(z);
    Zh[idx] = h;
    Zl[idx] = __float2bfloat16(z - __bfloat162float(h));
}

// ================= layernorm =================
__global__ void layernorm_kernel(const float* __restrict__ Zf,
                                 const float* __restrict__ gam, const float* __restrict__ bet,
                                 float* __restrict__ out)
{
    const ll row = blockIdx.x;
    const float* p = Zf + row * DMODEL;
    const int tid = threadIdx.x;
    float v[4];
    float s = 0.f, s2 = 0.f;
    #pragma unroll
    for (int i = 0; i < 4; i++) { v[i] = p[tid + i * 256]; s += v[i]; s2 += v[i] * v[i]; }
    __shared__ float rs[8], rs2[8];
    #pragma unroll
    for (int o = 16; o; o >>= 1) { s += __shfl_xor_sync(0xffffffffu, s, o);
                                   s2 += __shfl_xor_sync(0xffffffffu, s2, o); }
    if ((tid & 31) == 0) { rs[tid >> 5] = s; rs2[tid >> 5] = s2; }
    __syncthreads();
    float ts = 0.f, ts2 = 0.f;
    #pragma unroll
    for (int k = 0; k < 8; k++) { ts += rs[k]; ts2 += rs2[k]; }
    const float mu = ts * (1.f / DMODEL);
    const float var = ts2 * (1.f / DMODEL) - mu * mu;
    const float inv = rsqrtf(var + 1e-5f);
    #pragma unroll
    for (int i = 0; i < 4; i++) {
        int c = tid + i * 256;
        out[row * DMODEL + c] = (v[i] - mu) * inv * gam[c] + bet[c];
    }
}

// ================= launch =================
extern "C" void kernel_launch(void* const* d_in, const int* in_sizes, int n_in,
                              void* d_out, int out_size)
{
    (void)in_sizes; (void)n_in; (void)out_size;
    const float* x     = (const float*)d_in[0];
    const float* projW = (const float*)d_in[1];
    const float* projb = (const float*)d_in[2];
    const float* inW   = (const float*)d_in[3];
    const float* inb   = (const float*)d_in[4];
    const float* outW  = (const float*)d_in[5];
    const float* outb  = (const float*)d_in[6];
    const float* fusW  = (const float*)d_in[7];
    const float* fusb  = (const float*)d_in[8];
    const float* lng   = (const float*)d_in[9];
    const float* lnb   = (const float*)d_in[10];

    float* fused = (float*)d_out;
    float* w0 = fused + (ll)BATCH * SEQ * DMODEL;

    __nv_bfloat16 *xh,*xl,*PWth,*PWtl,*IWth,*IWtl,*OWth,*OWtl,*FWth,*FWtl;
    __nv_bfloat16 *Xsh,*Xsl,*Qh,*Ql,*Vth,*Vtl,*Sh,*Sl,*Oh,*Ol,*Zh,*Zl;
    float *Y,*ZF,*gM,*gIL;
    cudaGetSymbolAddress((void**)&xh, g_xh);   cudaGetSymbolAddress((void**)&xl, g_xl);
    cudaGetSymbolAddress((void**)&PWth, g_PWth); cudaGetSymbolAddress((void**)&PWtl, g_PWtl);
    cudaGetSymbolAddress((void**)&IWth, g_IWth); cudaGetSymbolAddress((void**)&IWtl, g_IWtl);
    cudaGetSymbolAddress((void**)&OWth, g_OWth); cudaGetSymbolAddress((void**)&OWtl, g_OWtl);
    cudaGetSymbolAddress((void**)&FWth, g_FWth); cudaGetSymbolAddress((void**)&FWtl, g_FWtl);
    cudaGetSymbolAddress((void**)&Xsh, g_Xsh); cudaGetSymbolAddress((void**)&Xsl, g_Xsl);
    cudaGetSymbolAddress((void**)&Qh, g_Qh);   cudaGetSymbolAddress((void**)&Ql, g_Ql);
    cudaGetSymbolAddress((void**)&Vth, g_Vth); cudaGetSymbolAddress((void**)&Vtl, g_Vtl);
    cudaGetSymbolAddress((void**)&Sh, g_Sh);   cudaGetSymbolAddress((void**)&Sl, g_Sl);
    cudaGetSymbolAddress((void**)&Oh, g_Oh);   cudaGetSymbolAddress((void**)&Ol, g_Ol);
    cudaGetSymbolAddress((void**)&Zh, g_Zh);   cudaGetSymbolAddress((void**)&Zl, g_Zl);
    cudaGetSymbolAddress((void**)&Y, g_Y);
    cudaGetSymbolAddress((void**)&ZF, g_ZF);
    cudaGetSymbolAddress((void**)&gM, g_M);
    cudaGetSymbolAddress((void**)&gIL, g_IL);

    const dim3 blk(256);
    const dim3 tblk(32, 8);

    const int smem128 = 2 * (2 * 128 * 40 + 2 * 128 * 40) * 2;   // 81920
    const int smemFlash = (4 * 128 * 72 + 2 * 64 * 136) * 2;      // 108544
    cudaFuncSetAttribute(tc_gemm<128>, cudaFuncAttributeMaxDynamicSharedMemorySize, smem128);
    cudaFuncSetAttribute(flash_kernel<0>, cudaFuncAttributeMaxDynamicSharedMemorySize, smemFlash);
    cudaFuncSetAttribute(flash_kernel<1>, cudaFuncAttributeMaxDynamicSharedMemorySize, smemFlash);

    split_kernel<<<(unsigned)(((ll)BATCH*SEQ*DMODEL + 255) / 256), blk>>>(x, xh, xl, (ll)BATCH*SEQ*DMODEL);
    transpose_split<<<dim3(EE/32, DMODEL/32, NSC), tblk>>>(projW, (ll)DMODEL*EE, PWth, PWtl, (ll)EE*DMODEL, DMODEL, EE);
    transpose_split<<<dim3(768/32, EE/32, NSC), tblk>>>(inW, (ll)EE*768, IWth, IWtl, (ll)768*EE, EE, 768);
    transpose_split<<<dim3(EE/32, EE/32, NSC), tblk>>>(outW, (ll)EE*EE, OWth, OWtl, (ll)EE*EE, EE, EE);
    transpose_split<<<dim3(DMODEL/32, DMODEL/32, 1), tblk>>>(fusW, 0, FWth, FWtl, 0, DMODEL, DMODEL);

    int yoff = 0;
    for (int i = 0; i < NSC; i++) {
        const int s = 1 << i;
        const int L = SEQ >> i;
        const int rows = BATCH * L;

        // proj: (rows,1024)@(1024,256) -> Xs hi/lo
        tc_gemm<128><<<dim3(EE/128, rows/128, 1), blk, smem128>>>(
            DMODEL, L, (ll)s * DMODEL, (ll)SEQ * DMODEL,
            xh, xl, 0, 0,
            PWth + (ll)i*EE*DMODEL, PWtl + (ll)i*EE*DMODEL, DMODEL, 0, 0,
            projb + i * EE, nullptr, Xsh, Xsl, EE, 0, 0, 1.f);

        // qkv: (rows,256)@(256,768) -> Q hi/lo
        tc_gemm<128><<<dim3(768/128, rows/128, 1), blk, smem128>>>(
            EE, rows, (ll)EE, 0,
            Xsh, Xsl, 0, 0,
            IWth + (ll)i*768*EE, IWtl + (ll)i*768*EE, EE, 0, 0,
            inb + i * 768, nullptr, Qh, Ql, 768, 0, 0, 1.f);

        // V transpose
        vtrans_kernel<<<dim3(L/32, 2, 16), tblk>>>(Qh, Ql, Vth, Vtl, L);

        // fused flash attention -> O hi/lo (+ S export for scale 0)
        if (i == 0)
            flash_kernel<1><<<dim3(L/128, 16), blk, smemFlash>>>(
                L, Qh, Ql, Vth, Vtl, Oh, Ol, Sh, Sl, gM, gIL);
        else
            flash_kernel<0><<<dim3(L/128, 16), blk, smemFlash>>>(
                L, Qh, Ql, Vth, Vtl, Oh, Ol, nullptr, nullptr, nullptr, nullptr);

        if (i == 0)
            w0_kernel<<<(unsigned)(((ll)BATCH*SEQ*SEQ) / 256), blk>>>(Sh, Sl, gM, gIL, w0);

        // out proj: (rows,256)@(256,256) -> Y fp32
        tc_gemm<128><<<dim3(EE/128, rows/128, 1), blk, smem128>>>(
            EE, rows, (ll)EE, 0,
            Oh, Ol, 0, 0,
            OWth + (ll)i*EE*EE, OWtl + (ll)i*EE*EE, EE, 0, 0,
            outb + i * EE, Y + (ll)yoff * EE, nullptr, nullptr, EE, 0, 0, 1.f);

        yoff += rows;
    }

    // upsample + concat -> Z hi/lo
    upsample_kernel<<<(unsigned)(((ll)BATCH*SEQ*DMODEL) / 256), blk>>>(Y, Zh, Zl);

    // fusion: (8192,1024)@(1024,1024) -> ZF fp32
    tc_gemm<128><<<dim3(DMODEL/128, (BATCH*SEQ)/128, 1), blk, smem128>>>(
        DMODEL, BATCH * SEQ, (ll)DMODEL, 0,
        Zh, Zl, 0, 0,
        FWth, FWtl, DMODEL, 0, 0,
        fusb, ZF, nullptr, nullptr, DMODEL, 0, 0, 1.f);

    // layernorm -> fused output
    layernorm_kernel<<<BATCH * SEQ, blk>>>(ZF, lng, lnb, fused);
}